// round 5
// baseline (speedup 1.0000x reference)
#include <cuda_runtime.h>
#include <math.h>
#include <stdint.h>

// ---------------- model constants ----------------
#define BB 4
#define NSEQ 1024
#define DD 1024
#define LL 6
#define HH 8
#define GG 4
#define RK 64
#define SS 128
#define RR 256
#define DHD 128
#define VV 32000
#define BT (BB*NSEQ)          // 4096 token rows
#define LOGIC_STRENGTH 0.02f

typedef unsigned long long u64;

// ---------------- scratch (static device memory; no allocations) ----------------
__device__ float g_x [BT*DD];
__device__ float g_hb[BT*DD];
__device__ float g_t0[BT*DD];
__device__ float g_br[BT*DD];
__device__ float g_q [BT*512];
__device__ float g_k [BT*256];
__device__ float g_v [BT*512];
__device__ float g_p [(size_t)32*NSEQ*NSEQ];   // [b,g,u,n,m] scores/probs (134 MB)
__device__ float g_u [BT*SS];
__device__ float g_hs[BT*SS];
__device__ float g_xz[BT*RR];
__device__ float g_xh[BT*RR];
__device__ float g_hr[BT*RR];
__device__ float g_bias[NSEQ*NSEQ];
__device__ float g_weff[DD*DD];

// ---------------- packed fp32x2 helpers (Blackwell FFMA2 path) ----------------
__device__ __forceinline__ void ffma2(u64& d, u64 a, u64 b) {
    asm("fma.rn.f32x2 %0, %1, %2, %3;" : "=l"(d) : "l"(a), "l"(b), "l"(d));
}
__device__ __forceinline__ u64 pack2(float lo, float hi) {
    u64 r;
    asm("mov.b64 %0, {%1, %2};" : "=l"(r) : "f"(lo), "f"(hi));
    return r;
}
__device__ __forceinline__ void unpack2(float& lo, float& hi, u64 v) {
    asm("mov.b64 {%0, %1}, %2;" : "=f"(lo), "=f"(hi) : "l"(v));
}

// ---------------- generic tiled SGEMM: 128x128x16, 256 thr, 8x8/thread ----------
// Double-buffered smem pipeline: one BAR.SYNC per k-tile, next-tile LDGs issued
// before current-tile compute so DRAM/L2 latency overlaps the FFMA2 mainloop.
#define EPI_STORE 0
#define EPI_ACC   1
#define EPI_SCORE 2
#define EPI_BVEC  3

template<bool TB, int EPI>
__global__ __launch_bounds__(256)
void gemm_k(const float* __restrict__ A, int lda, long a0, long a1, long a2,
            const float* __restrict__ B, int ldb, long b0, long b1, long b2,
            float* __restrict__ C, int ldc, long c0, long c1, long c2,
            int r1, int r2, int K, int causal,
            const float* __restrict__ E, float scale)
{
    const int bz = blockIdx.z;
    const int z2 = bz % r2;
    const int zt = bz / r2;
    const int z1 = zt % r1;
    const int z0 = zt / r1;
    A += (size_t)z0*a0 + (size_t)z1*a1 + (size_t)z2*a2;
    B += (size_t)z0*b0 + (size_t)z1*b1 + (size_t)z2*b2;
    C += (size_t)z0*c0 + (size_t)z1*c1 + (size_t)z2*c2;

    const int m0 = blockIdx.y * 128;
    const int n0 = blockIdx.x * 128;
    const int tid = threadIdx.x;
    const int tm = (tid >> 4) << 3;
    const int tn = (tid & 15) << 3;

    if (EPI == EPI_SCORE && n0 > m0) {   // tile entirely above diagonal -> fully masked
        #pragma unroll
        for (int i = 0; i < 8; i++)
            #pragma unroll
            for (int j = 0; j < 8; j++)
                C[(size_t)(m0+tm+i)*ldc + (n0+tn+j)] = -1e9f;
        return;
    }

    // causal: softmax rows are exactly 0 beyond the diagonal -> truncate K
    const int Keff = causal ? ((m0 + 128 < K) ? (m0 + 128) : K) : K;

    __shared__ __align__(16) float As[2][16][132];
    __shared__ __align__(16) float Bs[2][16][136];

    u64 acc2[8][4];
    #pragma unroll
    for (int i = 0; i < 8; i++)
        #pragma unroll
        for (int jp = 0; jp < 4; jp++) acc2[i][jp] = 0ull;

    // per-thread load coordinates
    const int arow = tid >> 2;            // 0..63
    const int acol = (tid & 3) << 2;      // 0,4,8,12
    const int brow = tid >> 5;            // 0..7   (non-TB)
    const int bcol = (tid & 31) << 2;     // 0..124 (non-TB)
    const int tbrow = tid >> 1;           // 0..127 (TB)
    const int tbcol = (tid & 1) << 3;     // 0,8    (TB)

    float4 la0, la1, lb0, lb1;

    // ---- prologue: load k-tile 0 into registers, then smem[0] ----
    la0 = *(const float4*)(A + (size_t)(m0 + arow     )*lda + acol);
    la1 = *(const float4*)(A + (size_t)(m0 + arow + 64)*lda + acol);
    if (!TB) {
        lb0 = *(const float4*)(B + (size_t)(brow    )*ldb + n0 + bcol);
        lb1 = *(const float4*)(B + (size_t)(brow + 8)*ldb + n0 + bcol);
    } else {
        const float* bp = B + (size_t)(n0 + tbrow)*ldb + tbcol;
        lb0 = *(const float4*)(bp);
        lb1 = *(const float4*)(bp + 4);
    }
    {
        As[0][acol+0][arow] = la0.x; As[0][acol+1][arow] = la0.y;
        As[0][acol+2][arow] = la0.z; As[0][acol+3][arow] = la0.w;
        As[0][acol+0][arow+64] = la1.x; As[0][acol+1][arow+64] = la1.y;
        As[0][acol+2][arow+64] = la1.z; As[0][acol+3][arow+64] = la1.w;
        if (!TB) {
            *(float4*)&Bs[0][brow  ][bcol] = lb0;
            *(float4*)&Bs[0][brow+8][bcol] = lb1;
        } else {
            Bs[0][tbcol+0][tbrow] = lb0.x; Bs[0][tbcol+1][tbrow] = lb0.y;
            Bs[0][tbcol+2][tbrow] = lb0.z; Bs[0][tbcol+3][tbrow] = lb0.w;
            Bs[0][tbcol+4][tbrow] = lb1.x; Bs[0][tbcol+5][tbrow] = lb1.y;
            Bs[0][tbcol+6][tbrow] = lb1.z; Bs[0][tbcol+7][tbrow] = lb1.w;
        }
    }
    __syncthreads();

    int buf = 0;
    for (int k0 = 0; k0 < Keff; k0 += 16, buf ^= 1) {
        const bool more = (k0 + 16) < Keff;
        // ---- issue next-tile global loads early (latency overlaps compute) ----
        if (more) {
            const int kn = k0 + 16;
            la0 = *(const float4*)(A + (size_t)(m0 + arow     )*lda + kn + acol);
            la1 = *(const float4*)(A + (size_t)(m0 + arow + 64)*lda + kn + acol);
            if (!TB) {
                lb0 = *(const float4*)(B + (size_t)(kn + brow    )*ldb + n0 + bcol);
                lb1 = *(const float4*)(B + (size_t)(kn + brow + 8)*ldb + n0 + bcol);
            } else {
                const float* bp = B + (size_t)(n0 + tbrow)*ldb + kn + tbcol;
                lb0 = *(const float4*)(bp);
                lb1 = *(const float4*)(bp + 4);
            }
        }
        // ---- compute current tile from smem[buf] ----
        #pragma unroll
        for (int kk = 0; kk < 16; kk++) {
            float a[8];
            *(float4*)(a)   = *(const float4*)&As[buf][kk][tm];
            *(float4*)(a+4) = *(const float4*)&As[buf][kk][tm+4];
            u64 b2[4];
            {
                const float4 vb0 = *(const float4*)&Bs[buf][kk][tn];
                const float4 vb1 = *(const float4*)&Bs[buf][kk][tn+4];
                b2[0] = pack2(vb0.x, vb0.y);
                b2[1] = pack2(vb0.z, vb0.w);
                b2[2] = pack2(vb1.x, vb1.y);
                b2[3] = pack2(vb1.z, vb1.w);
            }
            #pragma unroll
            for (int i = 0; i < 8; i++) {
                const u64 a2 = pack2(a[i], a[i]);
                ffma2(acc2[i][0], a2, b2[0]);
                ffma2(acc2[i][1], a2, b2[1]);
                ffma2(acc2[i][2], a2, b2[2]);
                ffma2(acc2[i][3], a2, b2[3]);
            }
        }
        if (!more) break;
        // ---- store next tile into alternate buffer, single barrier per tile ----
        {
            const int nb = buf ^ 1;
            As[nb][acol+0][arow] = la0.x; As[nb][acol+1][arow] = la0.y;
            As[nb][acol+2][arow] = la0.z; As[nb][acol+3][arow] = la0.w;
            As[nb][acol+0][arow+64] = la1.x; As[nb][acol+1][arow+64] = la1.y;
            As[nb][acol+2][arow+64] = la1.z; As[nb][acol+3][arow+64] = la1.w;
            if (!TB) {
                *(float4*)&Bs[nb][brow  ][bcol] = lb0;
                *(float4*)&Bs[nb][brow+8][bcol] = lb1;
            } else {
                Bs[nb][tbcol+0][tbrow] = lb0.x; Bs[nb][tbcol+1][tbrow] = lb0.y;
                Bs[nb][tbcol+2][tbrow] = lb0.z; Bs[nb][tbcol+3][tbrow] = lb0.w;
                Bs[nb][tbcol+4][tbrow] = lb1.x; Bs[nb][tbcol+5][tbrow] = lb1.y;
                Bs[nb][tbcol+6][tbrow] = lb1.z; Bs[nb][tbcol+7][tbrow] = lb1.w;
            }
        }
        __syncthreads();
    }

    // --- epilogue ---
    #pragma unroll
    for (int i = 0; i < 8; i++) {
        const int row = m0 + tm + i;
        float* cp = C + (size_t)row*ldc + n0 + tn;
        float acc[8];
        #pragma unroll
        for (int jp = 0; jp < 4; jp++) unpack2(acc[2*jp], acc[2*jp+1], acc2[i][jp]);
        if (EPI == EPI_STORE) {
            #pragma unroll
            for (int j = 0; j < 8; j++) cp[j] = acc[j];
        } else if (EPI == EPI_ACC) {
            #pragma unroll
            for (int j = 0; j < 8; j++) cp[j] += acc[j];
        } else if (EPI == EPI_SCORE) {
            #pragma unroll
            for (int j = 0; j < 8; j++) {
                const int col = n0 + tn + j;
                cp[j] = (col <= row) ? fmaf(acc[j], scale, E[(size_t)row*NSEQ + col])
                                     : -1e9f;
            }
        } else { // EPI_BVEC
            #pragma unroll
            for (int j = 0; j < 8; j++) cp[j] = acc[j] + E[n0 + tn + j];
        }
    }
}

// ---------------- small kernels ----------------
__global__ void embed_kernel(const int* __restrict__ tok, const float* __restrict__ emb,
                             float* __restrict__ x)
{
    const int row = blockIdx.x;
    const int t = tok[row];
    const float4* src = (const float4*)(emb + (size_t)t*DD);
    float4* dst = (float4*)(x + (size_t)row*DD);
    dst[threadIdx.x] = src[threadIdx.x];
}

__global__ void bias_kernel(const float* __restrict__ pb_a, const float* __restrict__ pb_w,
                            float* __restrict__ bias)
{
    const int idx = blockIdx.x * 256 + threadIdx.x;
    const int n = idx >> 10;
    const int m = idx & 1023;
    const float dn = fabsf((float)(n - m)) * (1.0f / (float)NSEQ);
    const float pi = 3.14159265358979323846f;
    float v = -pb_a[0] * dn * dn;
    v += pb_w[0] * sinf(pi * 1.f * dn);
    v += pb_w[1] * sinf(pi * 2.f * dn);
    v += pb_w[2] * sinf(pi * 3.f * dn);
    bias[idx] = v;
}

__global__ void weff_kernel(const float* __restrict__ alpha, const float* __restrict__ c,
                            const float* __restrict__ Wpc, float* __restrict__ w)
{
    const int idx = blockIdx.x * 256 + threadIdx.x;
    const float s = alpha[0];
    w[idx] = s * (c[0]*Wpc[idx] + c[1]*Wpc[idx + 1048576] + c[2]*Wpc[idx + 2097152]);
}

__global__ void vec_add(float* __restrict__ x, const float* __restrict__ t)
{
    const size_t i = (size_t)(blockIdx.x * 256 + threadIdx.x);
    float4 a = ((const float4*)x)[i];
    float4 b = ((const float4*)t)[i];
    a.x += b.x; a.y += b.y; a.z += b.z; a.w += b.w;
    ((float4*)x)[i] = a;
}

__global__ void vec_add_tanh(float* __restrict__ x, const float* __restrict__ t)
{
    const size_t i = (size_t)(blockIdx.x * 256 + threadIdx.x);
    float4 a = ((const float4*)x)[i];
    float4 b = ((const float4*)t)[i];
    a.x += LOGIC_STRENGTH * tanhf(b.x);
    a.y += LOGIC_STRENGTH * tanhf(b.y);
    a.z += LOGIC_STRENGTH * tanhf(b.z);
    a.w += LOGIC_STRENGTH * tanhf(b.w);
    ((float4*)x)[i] = a;
}

__global__ void vec_add_scaled(float* __restrict__ x, const float* __restrict__ t,
                               const float* __restrict__ scales, int l)
{
    const float s = scales[l];
    const size_t i = (size_t)(blockIdx.x * 256 + threadIdx.x);
    float4 a = ((const float4*)x)[i];
    float4 b = ((const float4*)t)[i];
    a.x += s * b.x; a.y += s * b.y; a.z += s * b.z; a.w += s * b.w;
    ((float4*)x)[i] = a;
}

// LayerNorm over D=1024, one block (256 thr) per row
__global__ __launch_bounds__(256)
void ln_kernel(const float* __restrict__ x, const float* __restrict__ g,
               const float* __restrict__ b, float* __restrict__ y)
{
    const int row = blockIdx.x;
    const float* xr = x + (size_t)row*DD;
    float v[4], s = 0.f, sq = 0.f;
    #pragma unroll
    for (int i = 0; i < 4; i++) {
        v[i] = xr[threadIdx.x + i*256];
        s += v[i]; sq += v[i]*v[i];
    }
    __shared__ float red[16];
    #pragma unroll
    for (int o = 16; o > 0; o >>= 1) {
        s  += __shfl_down_sync(0xffffffffu, s,  o);
        sq += __shfl_down_sync(0xffffffffu, sq, o);
    }
    const int w = threadIdx.x >> 5, lane = threadIdx.x & 31;
    if (lane == 0) { red[w] = s; red[8 + w] = sq; }
    __syncthreads();
    if (threadIdx.x == 0) {
        float ts = 0.f, tq = 0.f;
        #pragma unroll
        for (int k = 0; k < 8; k++) { ts += red[k]; tq += red[8 + k]; }
        red[0] = ts; red[8] = tq;
    }
    __syncthreads();
    const float mean = red[0] * (1.f/1024.f);
    const float var  = red[8] * (1.f/1024.f) - mean*mean;
    const float inv  = rsqrtf(var + 1e-5f);
    float* yr = y + (size_t)row*DD;
    #pragma unroll
    for (int i = 0; i < 4; i++) {
        const int d = threadIdx.x + i*256;
        yr[d] = (v[i] - mean) * inv * g[d] + b[d];
    }
}

// softmax over 1024-wide row, one block (128 thr) per row
__global__ __launch_bounds__(128)
void softmax_kernel(float* __restrict__ p)
{
    float* row = p + (size_t)blockIdx.x * NSEQ;
    float v[8];
    float4 u0 = *(float4*)&row[threadIdx.x*4];
    float4 u1 = *(float4*)&row[512 + threadIdx.x*4];
    v[0]=u0.x; v[1]=u0.y; v[2]=u0.z; v[3]=u0.w;
    v[4]=u1.x; v[5]=u1.y; v[6]=u1.z; v[7]=u1.w;
    float mx = v[0];
    #pragma unroll
    for (int i = 1; i < 8; i++) mx = fmaxf(mx, v[i]);
    __shared__ float red[8];
    #pragma unroll
    for (int o = 16; o > 0; o >>= 1) mx = fmaxf(mx, __shfl_down_sync(0xffffffffu, mx, o));
    const int w = threadIdx.x >> 5, lane = threadIdx.x & 31;
    if (lane == 0) red[w] = mx;
    __syncthreads();
    if (threadIdx.x == 0) red[0] = fmaxf(fmaxf(red[0], red[1]), fmaxf(red[2], red[3]));
    __syncthreads();
    mx = red[0];
    float s = 0.f;
    #pragma unroll
    for (int i = 0; i < 8; i++) { v[i] = expf(v[i] - mx); s += v[i]; }
    #pragma unroll
    for (int o = 16; o > 0; o >>= 1) s += __shfl_down_sync(0xffffffffu, s, o);
    if (lane == 0) red[4 + w] = s;
    __syncthreads();
    if (threadIdx.x == 0) red[4] = red[4] + red[5] + red[6] + red[7];
    __syncthreads();
    const float inv = 1.f / red[4];
    u0.x=v[0]*inv; u0.y=v[1]*inv; u0.z=v[2]*inv; u0.w=v[3]*inv;
    u1.x=v[4]*inv; u1.y=v[5]*inv; u1.z=v[6]*inv; u1.w=v[7]*inv;
    *(float4*)&row[threadIdx.x*4] = u0;
    *(float4*)&row[512 + threadIdx.x*4] = u1;
}

// diagonal SSM scan: one block per batch, thread = state index
__global__ __launch_bounds__(128)
void ssm_scan_kernel(const float* __restrict__ u, const float* __restrict__ alog,
                     float* __restrict__ hs)
{
    const int b = blockIdx.x, s = threadIdx.x;
    const float a = 1.f / (1.f + expf(-alog[s]));
    const float* ub = u  + (size_t)b*NSEQ*SS + s;
    float*       hb = hs + (size_t)b*NSEQ*SS + s;
    float h = 0.f;
    #pragma unroll 4
    for (int t = 0; t < NSEQ; t++) {
        h = fmaf(a, h, ub[(size_t)t*SS]);
        hb[(size_t)t*SS] = h;
    }
}

// ---------------- gated RNN scan: 4-CTA cluster per batch, U register-resident ----
__device__ __forceinline__ uint32_t smem_u32(const void* p) {
    uint32_t a;
    asm("{ .reg .u64 t; cvta.to.shared.u64 t, %1; cvt.u32.u64 %0, t; }" : "=r"(a) : "l"(p));
    return a;
}

__global__ void __cluster_dims__(4, 1, 1) __launch_bounds__(512, 1)
rnn_scan_cluster(const float* __restrict__ xz, const float* __restrict__ xh,
                 const float* __restrict__ Uz, const float* __restrict__ Uh,
                 float* __restrict__ hr)
{
    uint32_t crank;
    asm("mov.u32 %0, %%cluster_ctarank;" : "=r"(crank));
    const int b   = blockIdx.x >> 2;
    const int tid = threadIdx.x;
    const int j   = tid & 63;
    const int ig  = tid >> 6;
    const int jg  = (int)crank * 64 + j;
    const int i0  = ig * 32;

    // register-resident U slices (coalesced loads: consecutive j -> consecutive addr)
    float uz[32], uh[32];
    #pragma unroll
    for (int il = 0; il < 32; il++) {
        uz[il] = Uz[(size_t)(i0 + il)*RR + jg];
        uh[il] = Uh[(size_t)(i0 + il)*RR + jg];
    }

    __shared__ __align__(16) float hbuf[2][RR];
    __shared__ float pz[8][64], ph[8][64];
    if (tid < RR) { hbuf[0][tid] = 0.f; hbuf[1][tid] = 0.f; }
    __syncthreads();
    asm volatile("barrier.cluster.arrive.aligned;" ::: "memory");
    asm volatile("barrier.cluster.wait.aligned;"   ::: "memory");

    const float* xzb = xz + (size_t)b*NSEQ*RR;
    const float* xhb = xh + (size_t)b*NSEQ*RR;
    float*       hrb = hr + (size_t)b*NSEQ*RR;

    for (int t = 0; t < NSEQ; t++) {
        const float* hc = hbuf[t & 1];
        float az = 0.f, ah = 0.f;
        #pragma unroll
        for (int il = 0; il < 32; il += 4) {
            const float4 hv = *(const float4*)&hc[i0 + il];
            az = fmaf(hv.x, uz[il+0], az);  ah = fmaf(hv.x, uh[il+0], ah);
            az = fmaf(hv.y, uz[il+1], az);  ah = fmaf(hv.y, uh[il+1], ah);
            az = fmaf(hv.z, uz[il+2], az);  ah = fmaf(hv.z, uh[il+2], ah);
            az = fmaf(hv.w, uz[il+3], az);  ah = fmaf(hv.w, uh[il+3], ah);
        }
        pz[ig][j] = az;
        ph[ig][j] = ah;
        __syncthreads();
        if (tid < 64) {
            const int jmy = (int)crank * 64 + tid;
            float sz = 0.f, sh = 0.f;
            #pragma unroll
            for (int q = 0; q < 8; q++) { sz += pz[q][tid]; sh += ph[q][tid]; }
            const float hp = hc[jmy];
            const float zp = xzb[(size_t)t*RR + jmy] + sz;
            const float hpre = xhb[(size_t)t*RR + jmy] + sh;
            const float z  = 1.f / (1.f + expf(-zp));
            const float hn = (1.f - z)*hp + z*tanhf(hpre);
            // publish hn into next buffer of ALL 4 CTAs (incl. self) via DSMEM
            const uint32_t la = smem_u32(&hbuf[(t + 1) & 1][jmy]);
            #pragma unroll
            for (int r = 0; r < 4; r++) {
                uint32_t pa;
                asm volatile("mapa.shared::cluster.u32 %0, %1, %2;" : "=r"(pa) : "r"(la), "r"(r));
                asm volatile("st.shared::cluster.f32 [%0], %1;" :: "r"(pa), "f"(hn));
            }
            hrb[(size_t)t*RR + jmy] = hn;
        }
        asm volatile("barrier.cluster.arrive.aligned;" ::: "memory");
        asm volatile("barrier.cluster.wait.aligned;"   ::: "memory");
    }
}

// ---------------- host-side dispatch ----------------
struct Bo { long s0, s1, s2; };

static void launch_gemm(bool tb, int epi, int M, int N, int K,
                        const float* A, int lda, Bo ba,
                        const float* B, int ldb, Bo bb,
                        float* C, int ldc, Bo bc,
                        int r1, int r2, int nbatch, int causal,
                        const float* E, float scale)
{
    dim3 grid(N/128, M/128, nbatch);
#define GK(TBV, EPV) gemm_k<TBV, EPV><<<grid, 256>>>(A, lda, ba.s0, ba.s1, ba.s2, \
        B, ldb, bb.s0, bb.s1, bb.s2, C, ldc, bc.s0, bc.s1, bc.s2, r1, r2, K, causal, E, scale)
    if (!tb) {
        if      (epi == EPI_STORE) GK(false, EPI_STORE);
        else if (epi == EPI_ACC)   GK(false, EPI_ACC);
        else if (epi == EPI_SCORE) GK(false, EPI_SCORE);
        else                       GK(false, EPI_BVEC);
    } else {
        if      (epi == EPI_STORE) GK(true, EPI_STORE);
        else if (epi == EPI_ACC)   GK(true, EPI_ACC);
        else if (epi == EPI_SCORE) GK(true, EPI_SCORE);
        else                       GK(true, EPI_BVEC);
    }
#undef GK
}

static const Bo B0 = {0, 0, 0};

extern "C" void kernel_launch(void* const* d_in, const int* in_sizes, int n_in,
                              void* d_out, int out_size)
{
    const int*   tokens   = (const int*)  d_in[0];
    const float* embed    = (const float*)d_in[1];
    const float* pb_a     = (const float*)d_in[2];
    const float* pb_w     = (const float*)d_in[3];
    const float* pc_alpha = (const float*)d_in[4];
    const float* W_pc     = (const float*)d_in[5];
    const float* c_pc     = (const float*)d_in[6];
    const float* W_logic  = (const float*)d_in[7];
    const float* ln_g     = (const float*)d_in[8];
    const float* ln_b     = (const float*)d_in[9];
    const float* Wq       = (const float*)d_in[10];
    const float* Wk       = (const float*)d_in[11];
    const float* Wv       = (const float*)d_in[12];
    const float* Wo       = (const float*)d_in[13];
    const float* a_logit  = (const float*)d_in[14];
    const float* Win_ssm  = (const float*)d_in[15];
    const float* Wout_ssm = (const float*)d_in[16];
    const float* Wz       = (const float*)d_in[17];
    const float* Uz       = (const float*)d_in[18];
    const float* Wh       = (const float*)d_in[19];
    const float* Uh       = (const float*)d_in[20];
    const float* Wout_rnn = (const float*)d_in[21];
    const float* res_sc   = (const float*)d_in[22];
    const float* fg       = (const float*)d_in[23];
    const float* fb       = (const float*)d_in[24];
    const float* out_b    = (const float*)d_in[25];
    float* out = (float*)d_out;

    void* pv;
    float *x, *h, *t0, *br, *q, *k, *v, *p, *u, *hs, *xz, *xh, *hr, *bias, *weff;
    cudaGetSymbolAddress(&pv, g_x);    x   = (float*)pv;
    cudaGetSymbolAddress(&pv, g_hb);   h   = (float*)pv;
    cudaGetSymbolAddress(&pv, g_t0);   t0  = (float*)pv;
    cudaGetSymbolAddress(&pv, g_br);   br  = (float*)pv;
    cudaGetSymbolAddress(&pv, g_q);    q   = (float*)pv;
    cudaGetSymbolAddress(&pv, g_k);    k   = (float*)pv;
    cudaGetSymbolAddress(&pv, g_v);    v   = (float*)pv;
    cudaGetSymbolAddress(&pv, g_p);    p   = (float*)pv;
    cudaGetSymbolAddress(&pv, g_u);    u   = (float*)pv;
    cudaGetSymbolAddress(&pv, g_hs);   hs  = (float*)pv;
    cudaGetSymbolAddress(&pv, g_xz);   xz  = (float*)pv;
    cudaGetSymbolAddress(&pv, g_xh);   xh  = (float*)pv;
    cudaGetSymbolAddress(&pv, g_hr);   hr  = (float*)pv;
    cudaGetSymbolAddress(&pv, g_bias); bias= (float*)pv;
    cudaGetSymbolAddress(&pv, g_weff); weff= (float*)pv;

    // ---- precompute positional bias and combined PC projection ----
    bias_kernel<<<4096, 256>>>(pb_a, pb_w, bias);
    weff_kernel<<<4096, 256>>>(pc_alpha, c_pc, W_pc, weff);

    // ---- embed + front projections ----
    embed_kernel<<<BT, 256>>>(tokens, embed, x);
    launch_gemm(false, EPI_STORE, BT, DD, DD, x, DD, B0, weff, DD, B0, t0, DD, B0, 1, 1, 1, 0, nullptr, 0.f);
    vec_add<<<4096, 256>>>(x, t0);
    launch_gemm(false, EPI_STORE, BT, DD, DD, x, DD, B0, W_logic, DD, B0, t0, DD, B0, 1, 1, 1, 0, nullptr, 0.f);
    vec_add_tanh<<<4096, 256>>>(x, t0);

    // ---- layers ----
    for (int l = 0; l < LL; l++) {
        const float* Wq_l = Wq + (size_t)l*DD*512;
        const float* Wk_l = Wk + (size_t)l*DD*256;
        const float* Wv_l = Wv + (size_t)l*DD*512;
        const float* Wo_l = Wo + (size_t)l*DD*DD;
        const float* Wi_l = Win_ssm  + (size_t)l*DD*SS;
        const float* Ws_l = Wout_ssm + (size_t)l*SS*DD;
        const float* Wz_l = Wz + (size_t)l*DD*RR;
        const float* Wh_l = Wh + (size_t)l*DD*RR;
        const float* Uz_l = Uz + (size_t)l*RR*RR;
        const float* Uh_l = Uh + (size_t)l*RR*RR;
        const float* Wr_l = Wout_rnn + (size_t)l*RR*DD;

        ln_kernel<<<BT, 256>>>(x, ln_g + (size_t)l*DD, ln_b + (size_t)l*DD, h);

        launch_gemm(false, EPI_STORE, BT, 512, DD, h, DD, B0, Wq_l, 512, B0, q, 512, B0, 1, 1, 1, 0, nullptr, 0.f);
        launch_gemm(false, EPI_STORE, BT, 256, DD, h, DD, B0, Wk_l, 256, B0, k, 256, B0, 1, 1, 1, 0, nullptr, 0.f);
        launch_gemm(false, EPI_STORE, BT, 512, DD, h, DD, B0, Wv_l, 512, B0, v, 512, B0, 1, 1, 1, 0, nullptr, 0.f);

        // scores: s[b,g,u] = q_slice [N,64] @ k_slice^T, *1/8 + bias, causal mask
        {
            Bo ba = {(long)NSEQ*512, 128, 64};                 // b, g, u strides into q
            Bo bb = {(long)NSEQ*256, 64, 0};                   // b, g strides into k
            Bo bc = {(long)8*NSEQ*NSEQ, (long)2*NSEQ*NSEQ, (long)NSEQ*NSEQ};
            launch_gemm(true, EPI_SCORE, NSEQ, NSEQ, RK, q, 512, ba, k, 256, bb,
                        p, NSEQ, bc, 4, 2, 32, 0, bias, 0.125f);
        }
        softmax_kernel<<<32*NSEQ, 128>>>(p);
        // o = p @ v  -> t0 laid out as [B,N, H*DH]; causal=1 truncates K at diag
        {
            Bo ba = {(long)8*NSEQ*NSEQ, (long)2*NSEQ*NSEQ, (long)NSEQ*NSEQ};
            Bo bb = {(long)NSEQ*512, 128, 0};
            Bo bc = {(long)NSEQ*DD, 256, 128};
            launch_gemm(false, EPI_STORE, NSEQ, DHD, NSEQ, p, NSEQ, ba, v, 512, bb,
                        t0, DD, bc, 4, 2, 32, 1, nullptr, 0.f);
        }
        launch_gemm(false, EPI_STORE, BT, DD, DD, t0, DD, B0, Wo_l, DD, B0, br, DD, B0, 1, 1, 1, 0, nullptr, 0.f);

        // SSM branch (from residual x)
        launch_gemm(false, EPI_STORE, BT, SS, DD, x, DD, B0, Wi_l, SS, B0, u, SS, B0, 1, 1, 1, 0, nullptr, 0.f);
        ssm_scan_kernel<<<BB, SS>>>(u, a_logit + (size_t)l*SS, hs);
        launch_gemm(false, EPI_ACC, BT, DD, SS, hs, SS, B0, Ws_l, DD, B0, br, DD, B0, 1, 1, 1, 0, nullptr, 0.f);

        // gated RNN branch (from residual x)
        launch_gemm(false, EPI_STORE, BT, RR, DD, x, DD, B0, Wz_l, RR, B0, xz, RR, B0, 1, 1, 1, 0, nullptr, 0.f);
        launch_gemm(false, EPI_STORE, BT, RR, DD, x, DD, B0, Wh_l, RR, B0, xh, RR, B0, 1, 1, 1, 0, nullptr, 0.f);
        rnn_scan_cluster<<<BB*4, 512>>>(xz, xh, Uz_l, Uh_l, hr);
        launch_gemm(false, EPI_ACC, BT, DD, RR, hr, RR, B0, Wr_l, DD, B0, br, DD, B0, 1, 1, 1, 0, nullptr, 0.f);

        vec_add_scaled<<<4096, 256>>>(x, br, res_sc, l);
    }

    // ---- final LN + tied head ----
    ln_kernel<<<BT, 256>>>(x, fg, fb, h);
    launch_gemm(true, EPI_BVEC, BT, VV, DD, h, DD, B0, embed, DD, B0, out, VV, B0, 1, 1, 1, 0, out_b, 0.f);
}

// round 8
// speedup vs baseline: 1.0935x; 1.0935x over previous
#include <cuda_runtime.h>
#include <math.h>
#include <stdint.h>

// ---------------- model constants ----------------
#define BB 4
#define NSEQ 1024
#define DD 1024
#define LL 6
#define HH 8
#define GG 4
#define RK 64
#define SS 128
#define RR 256
#define DHD 128
#define VV 32000
#define BT (BB*NSEQ)          // 4096 token rows
#define LOGIC_STRENGTH 0.02f

typedef unsigned long long u64;

// ---------------- scratch (static device memory; no allocations) ----------------
__device__ float g_x [BT*DD];
__device__ float g_hb[BT*DD];
__device__ float g_t0[BT*DD];
__device__ float g_br[BT*DD];
__device__ float g_q [BT*512];
__device__ float g_k [BT*256];
__device__ float g_v [BT*512];
__device__ float g_p [(size_t)32*NSEQ*NSEQ];   // [b,g,u,n,m] scores/probs (134 MB)
__device__ float g_u [BT*SS];
__device__ float g_hs[BT*SS];
__device__ float g_xz[BT*RR];
__device__ float g_xh[BT*RR];
__device__ float g_hr[BT*RR];
__device__ float g_bias[NSEQ*NSEQ];
__device__ float g_weff[DD*DD];

// ---------------- tf32 helpers (3xTF32 error-compensated path) ----------------
__device__ __forceinline__ uint32_t f2tf32(float f) {
    uint32_t r;
    asm("cvt.rna.tf32.f32 %0, %1;" : "=r"(r) : "f"(f));
    return r;
}
__device__ __forceinline__ void split_tf32(float x, uint32_t& hi, uint32_t& lo) {
    hi = f2tf32(x);
    lo = f2tf32(x - __uint_as_float(hi));
}

// D += A@B via tensor core, m16n8k8 tf32, fp32 accumulate
__device__ __forceinline__ void mma_tf32(float* c, const uint32_t* a, uint32_t b0, uint32_t b1) {
    asm volatile("mma.sync.aligned.m16n8k8.row.col.f32.tf32.tf32.f32 "
        "{%0,%1,%2,%3}, {%4,%5,%6,%7}, {%8,%9}, {%0,%1,%2,%3};"
        : "+f"(c[0]), "+f"(c[1]), "+f"(c[2]), "+f"(c[3])
        : "r"(a[0]), "r"(a[1]), "r"(a[2]), "r"(a[3]), "r"(b0), "r"(b1));
}

// ---------------- generic tiled GEMM via 3xTF32 tensor cores -----------------
// CTA tile 128x128, k-tile 16, 256 thr = 8 warps (4x2), warp tile 32x64.
// fp32 smem tiles; hi/lo tf32 split in registers; 3 MMAs per logical MMA.
#define EPI_STORE 0
#define EPI_ACC   1
#define EPI_SCORE 2
#define EPI_BVEC  3

template<bool TB, int EPI>
__global__ __launch_bounds__(256, 2)
void gemm_k(const float* __restrict__ A, int lda, long a0, long a1, long a2,
            const float* __restrict__ B, int ldb, long b0s, long b1s, long b2s,
            float* __restrict__ C, int ldc, long c0, long c1, long c2,
            int r1, int r2, int K, int causal,
            const float* __restrict__ E, float scale)
{
    const int bz = blockIdx.z;
    const int z2 = bz % r2;
    const int zt = bz / r2;
    const int z1 = zt % r1;
    const int z0 = zt / r1;
    A += (size_t)z0*a0 + (size_t)z1*a1 + (size_t)z2*a2;
    B += (size_t)z0*b0s + (size_t)z1*b1s + (size_t)z2*b2s;
    C += (size_t)z0*c0 + (size_t)z1*c1 + (size_t)z2*c2;

    const int m0 = blockIdx.x * 128;
    const int n0 = blockIdx.y * 128;
    const int tid = threadIdx.x;

    if (EPI == EPI_SCORE && n0 > m0) {   // tile entirely above diagonal
        for (int idx = tid; idx < 128*128; idx += 256)
            C[(size_t)(m0 + (idx >> 7))*ldc + n0 + (idx & 127)] = -1e9f;
        return;
    }

    const int Keff = causal ? ((m0 + 128 < K) ? (m0 + 128) : K) : K;

    __shared__ __align__(16) float As[2][16][132];   // [k][m] fp32
    __shared__ __align__(16) float Bs[2][16][136];   // [k][n] fp32

    const int lane = tid & 31;
    const int warp = tid >> 5;
    const int gid  = lane >> 2;     // 0..7
    const int tig  = lane & 3;      // 0..3
    const int wm   = (warp >> 1) * 32;   // 0,32,64,96
    const int wn   = (warp & 1) * 64;    // 0,64

    float acc[2][8][4];
    #pragma unroll
    for (int t = 0; t < 2; t++)
        #pragma unroll
        for (int j = 0; j < 8; j++)
            #pragma unroll
            for (int c = 0; c < 4; c++) acc[t][j][c] = 0.f;

    const int arow = tid >> 2;            // 0..63
    const int acol = (tid & 3) << 2;      // 0,4,8,12
    const int brow = tid >> 5;            // 0..7   (non-TB)
    const int bcol = (tid & 31) << 2;     // 0..124 (non-TB)
    const int tbrow = tid >> 1;           // 0..127 (TB)
    const int tbcol = (tid & 1) << 3;     // 0,8    (TB)

    float4 la0, la1, lb0, lb1;

    // ---- prologue: k-tile 0 -> smem[0] ----
    la0 = *(const float4*)(A + (size_t)(m0 + arow     )*lda + acol);
    la1 = *(const float4*)(A + (size_t)(m0 + arow + 64)*lda + acol);
    if (!TB) {
        lb0 = *(const float4*)(B + (size_t)(brow    )*ldb + n0 + bcol);
        lb1 = *(const float4*)(B + (size_t)(brow + 8)*ldb + n0 + bcol);
    } else {
        const float* bp = B + (size_t)(n0 + tbrow)*ldb + tbcol;
        lb0 = *(const float4*)(bp);
        lb1 = *(const float4*)(bp + 4);
    }
    {
        As[0][acol+0][arow] = la0.x; As[0][acol+1][arow] = la0.y;
        As[0][acol+2][arow] = la0.z; As[0][acol+3][arow] = la0.w;
        As[0][acol+0][arow+64] = la1.x; As[0][acol+1][arow+64] = la1.y;
        As[0][acol+2][arow+64] = la1.z; As[0][acol+3][arow+64] = la1.w;
        if (!TB) {
            *(float4*)&Bs[0][brow  ][bcol] = lb0;
            *(float4*)&Bs[0][brow+8][bcol] = lb1;
        } else {
            Bs[0][tbcol+0][tbrow] = lb0.x; Bs[0][tbcol+1][tbrow] = lb0.y;
            Bs[0][tbcol+2][tbrow] = lb0.z; Bs[0][tbcol+3][tbrow] = lb0.w;
            Bs[0][tbcol+4][tbrow] = lb1.x; Bs[0][tbcol+5][tbrow] = lb1.y;
            Bs[0][tbcol+6][tbrow] = lb1.z; Bs[0][tbcol+7][tbrow] = lb1.w;
        }
    }
    __syncthreads();

    int buf = 0;
    for (int k0 = 0; k0 < Keff; k0 += 16, buf ^= 1) {
        const bool more = (k0 + 16) < Keff;
        if (more) {
            const int kn = k0 + 16;
            la0 = *(const float4*)(A + (size_t)(m0 + arow     )*lda + kn + acol);
            la1 = *(const float4*)(A + (size_t)(m0 + arow + 64)*lda + kn + acol);
            if (!TB) {
                lb0 = *(const float4*)(B + (size_t)(kn + brow    )*ldb + n0 + bcol);
                lb1 = *(const float4*)(B + (size_t)(kn + brow + 8)*ldb + n0 + bcol);
            } else {
                const float* bp = B + (size_t)(n0 + tbrow)*ldb + kn + tbcol;
                lb0 = *(const float4*)(bp);
                lb1 = *(const float4*)(bp + 4);
            }
        }
        // ---- tensor compute on smem[buf]: two k8 chunks, 3xTF32 ----
        #pragma unroll
        for (int kc = 0; kc < 16; kc += 8) {
            uint32_t ah[2][4], al[2][4];
            #pragma unroll
            for (int t = 0; t < 2; t++) {
                const int m = wm + t*16 + gid;
                split_tf32(As[buf][kc+tig  ][m],   ah[t][0], al[t][0]);
                split_tf32(As[buf][kc+tig  ][m+8], ah[t][1], al[t][1]);
                split_tf32(As[buf][kc+tig+4][m],   ah[t][2], al[t][2]);
                split_tf32(As[buf][kc+tig+4][m+8], ah[t][3], al[t][3]);
            }
            #pragma unroll
            for (int j = 0; j < 8; j++) {
                const int n = wn + j*8 + gid;
                uint32_t bh0, bl0, bh1, bl1;
                split_tf32(Bs[buf][kc+tig  ][n], bh0, bl0);
                split_tf32(Bs[buf][kc+tig+4][n], bh1, bl1);
                #pragma unroll
                for (int t = 0; t < 2; t++) {
                    mma_tf32(acc[t][j], al[t], bh0, bh1);   // lo*hi
                    mma_tf32(acc[t][j], ah[t], bl0, bl1);   // hi*lo
                    mma_tf32(acc[t][j], ah[t], bh0, bh1);   // hi*hi (last: biggest term)
                }
            }
        }
        if (!more) break;
        {
            const int nb = buf ^ 1;
            As[nb][acol+0][arow] = la0.x; As[nb][acol+1][arow] = la0.y;
            As[nb][acol+2][arow] = la0.z; As[nb][acol+3][arow] = la0.w;
            As[nb][acol+0][arow+64] = la1.x; As[nb][acol+1][arow+64] = la1.y;
            As[nb][acol+2][arow+64] = la1.z; As[nb][acol+3][arow+64] = la1.w;
            if (!TB) {
                *(float4*)&Bs[nb][brow  ][bcol] = lb0;
                *(float4*)&Bs[nb][brow+8][bcol] = lb1;
            } else {
                Bs[nb][tbcol+0][tbrow] = lb0.x; Bs[nb][tbcol+1][tbrow] = lb0.y;
                Bs[nb][tbcol+2][tbrow] = lb0.z; Bs[nb][tbcol+3][tbrow] = lb0.w;
                Bs[nb][tbcol+4][tbrow] = lb1.x; Bs[nb][tbcol+5][tbrow] = lb1.y;
                Bs[nb][tbcol+6][tbrow] = lb1.z; Bs[nb][tbcol+7][tbrow] = lb1.w;
            }
        }
        __syncthreads();
    }

    // --- epilogue: (t,j,half) -> row = m0+wm+t*16+gid+half*8, col = n0+wn+j*8+tig*2 ---
    #pragma unroll
    for (int t = 0; t < 2; t++) {
        #pragma unroll
        for (int half = 0; half < 2; half++) {
            const int row = m0 + wm + t*16 + gid + half*8;
            #pragma unroll
            for (int j = 0; j < 8; j++) {
                const int col = n0 + wn + j*8 + tig*2;
                float v0 = acc[t][j][half*2 + 0];
                float v1 = acc[t][j][half*2 + 1];
                float* cp = C + (size_t)row*ldc + col;
                if (EPI == EPI_STORE) {
                    *(float2*)cp = make_float2(v0, v1);
                } else if (EPI == EPI_ACC) {
                    float2 old = *(float2*)cp;
                    *(float2*)cp = make_float2(old.x + v0, old.y + v1);
                } else if (EPI == EPI_SCORE) {
                    float r0 = (col     <= row) ? fmaf(v0, scale, E[(size_t)row*NSEQ + col    ]) : -1e9f;
                    float r1 = (col + 1 <= row) ? fmaf(v1, scale, E[(size_t)row*NSEQ + col + 1]) : -1e9f;
                    *(float2*)cp = make_float2(r0, r1);
                } else { // EPI_BVEC
                    *(float2*)cp = make_float2(v0 + E[col], v1 + E[col + 1]);
                }
            }
        }
    }
}

// ---------------- small kernels ----------------
__global__ void embed_kernel(const int* __restrict__ tok, const float* __restrict__ emb,
                             float* __restrict__ x)
{
    const int row = blockIdx.x;
    const int t = tok[row];
    const float4* src = (const float4*)(emb + (size_t)t*DD);
    float4* dst = (float4*)(x + (size_t)row*DD);
    dst[threadIdx.x] = src[threadIdx.x];
}

__global__ void bias_kernel(const float* __restrict__ pb_a, const float* __restrict__ pb_w,
                            float* __restrict__ bias)
{
    const int idx = blockIdx.x * 256 + threadIdx.x;
    const int n = idx >> 10;
    const int m = idx & 1023;
    const float dn = fabsf((float)(n - m)) * (1.0f / (float)NSEQ);
    const float pi = 3.14159265358979323846f;
    float v = -pb_a[0] * dn * dn;
    v += pb_w[0] * sinf(pi * 1.f * dn);
    v += pb_w[1] * sinf(pi * 2.f * dn);
    v += pb_w[2] * sinf(pi * 3.f * dn);
    bias[idx] = v;
}

__global__ void weff_kernel(const float* __restrict__ alpha, const float* __restrict__ c,
                            const float* __restrict__ Wpc, float* __restrict__ w)
{
    const int idx = blockIdx.x * 256 + threadIdx.x;
    const float s = alpha[0];
    w[idx] = s * (c[0]*Wpc[idx] + c[1]*Wpc[idx + 1048576] + c[2]*Wpc[idx + 2097152]);
}

__global__ void vec_add(float* __restrict__ x, const float* __restrict__ t)
{
    const size_t i = (size_t)(blockIdx.x * 256 + threadIdx.x);
    float4 a = ((const float4*)x)[i];
    float4 b = ((const float4*)t)[i];
    a.x += b.x; a.y += b.y; a.z += b.z; a.w += b.w;
    ((float4*)x)[i] = a;
}

__global__ void vec_add_tanh(float* __restrict__ x, const float* __restrict__ t)
{
    const size_t i = (size_t)(blockIdx.x * 256 + threadIdx.x);
    float4 a = ((const float4*)x)[i];
    float4 b = ((const float4*)t)[i];
    a.x += LOGIC_STRENGTH * tanhf(b.x);
    a.y += LOGIC_STRENGTH * tanhf(b.y);
    a.z += LOGIC_STRENGTH * tanhf(b.z);
    a.w += LOGIC_STRENGTH * tanhf(b.w);
    ((float4*)x)[i] = a;
}

__global__ void vec_add_scaled(float* __restrict__ x, const float* __restrict__ t,
                               const float* __restrict__ scales, int l)
{
    const float s = scales[l];
    const size_t i = (size_t)(blockIdx.x * 256 + threadIdx.x);
    float4 a = ((const float4*)x)[i];
    float4 b = ((const float4*)t)[i];
    a.x += s * b.x; a.y += s * b.y; a.z += s * b.z; a.w += s * b.w;
    ((float4*)x)[i] = a;
}

// LayerNorm over D=1024, one block (256 thr) per row
__global__ __launch_bounds__(256)
void ln_kernel(const float* __restrict__ x, const float* __restrict__ g,
               const float* __restrict__ b, float* __restrict__ y)
{
    const int row = blockIdx.x;
    const float* xr = x + (size_t)row*DD;
    float v[4], s = 0.f, sq = 0.f;
    #pragma unroll
    for (int i = 0; i < 4; i++) {
        v[i] = xr[threadIdx.x + i*256];
        s += v[i]; sq += v[i]*v[i];
    }
    __shared__ float red[16];
    #pragma unroll
    for (int o = 16; o > 0; o >>= 1) {
        s  += __shfl_down_sync(0xffffffffu, s,  o);
        sq += __shfl_down_sync(0xffffffffu, sq, o);
    }
    const int w = threadIdx.x >> 5, lane = threadIdx.x & 31;
    if (lane == 0) { red[w] = s; red[8 + w] = sq; }
    __syncthreads();
    if (threadIdx.x == 0) {
        float ts = 0.f, tq = 0.f;
        #pragma unroll
        for (int k = 0; k < 8; k++) { ts += red[k]; tq += red[8 + k]; }
        red[0] = ts; red[8] = tq;
    }
    __syncthreads();
    const float mean = red[0] * (1.f/1024.f);
    const float var  = red[8] * (1.f/1024.f) - mean*mean;
    const float inv  = rsqrtf(var + 1e-5f);
    float* yr = y + (size_t)row*DD;
    #pragma unroll
    for (int i = 0; i < 4; i++) {
        const int d = threadIdx.x + i*256;
        yr[d] = (v[i] - mean) * inv * g[d] + b[d];
    }
}

// softmax over 1024-wide row, one block (128 thr) per row
__global__ __launch_bounds__(128)
void softmax_kernel(float* __restrict__ p)
{
    float* row = p + (size_t)blockIdx.x * NSEQ;
    float v[8];
    float4 u0 = *(float4*)&row[threadIdx.x*4];
    float4 u1 = *(float4*)&row[512 + threadIdx.x*4];
    v[0]=u0.x; v[1]=u0.y; v[2]=u0.z; v[3]=u0.w;
    v[4]=u1.x; v[5]=u1.y; v[6]=u1.z; v[7]=u1.w;
    float mx = v[0];
    #pragma unroll
    for (int i = 1; i < 8; i++) mx = fmaxf(mx, v[i]);
    __shared__ float red[8];
    #pragma unroll
    for (int o = 16; o > 0; o >>= 1) mx = fmaxf(mx, __shfl_down_sync(0xffffffffu, mx, o));
    const int w = threadIdx.x >> 5, lane = threadIdx.x & 31;
    if (lane == 0) red[w] = mx;
    __syncthreads();
    if (threadIdx.x == 0) red[0] = fmaxf(fmaxf(red[0], red[1]), fmaxf(red[2], red[3]));
    __syncthreads();
    mx = red[0];
    float s = 0.f;
    #pragma unroll
    for (int i = 0; i < 8; i++) { v[i] = expf(v[i] - mx); s += v[i]; }
    #pragma unroll
    for (int o = 16; o > 0; o >>= 1) s += __shfl_down_sync(0xffffffffu, s, o);
    if (lane == 0) red[4 + w] = s;
    __syncthreads();
    if (threadIdx.x == 0) red[4] = red[4] + red[5] + red[6] + red[7];
    __syncthreads();
    const float inv = 1.f / red[4];
    u0.x=v[0]*inv; u0.y=v[1]*inv; u0.z=v[2]*inv; u0.w=v[3]*inv;
    u1.x=v[4]*inv; u1.y=v[5]*inv; u1.z=v[6]*inv; u1.w=v[7]*inv;
    *(float4*)&row[threadIdx.x*4] = u0;
    *(float4*)&row[512 + threadIdx.x*4] = u1;
}

// diagonal SSM scan: one block per batch, thread = state index
__global__ __launch_bounds__(128)
void ssm_scan_kernel(const float* __restrict__ u, const float* __restrict__ alog,
                     float* __restrict__ hs)
{
    const int b = blockIdx.x, s = threadIdx.x;
    const float a = 1.f / (1.f + expf(-alog[s]));
    const float* ub = u  + (size_t)b*NSEQ*SS + s;
    float*       hb = hs + (size_t)b*NSEQ*SS + s;
    float h = 0.f;
    #pragma unroll 4
    for (int t = 0; t < NSEQ; t++) {
        h = fmaf(a, h, ub[(size_t)t*SS]);
        hb[(size_t)t*SS] = h;
    }
}

// ---------------- gated RNN scan: 4-CTA cluster per batch, U register-resident ----
__device__ __forceinline__ uint32_t smem_u32(const void* p) {
    uint32_t a;
    asm("{ .reg .u64 t; cvta.to.shared.u64 t, %1; cvt.u32.u64 %0, t; }" : "=r"(a) : "l"(p));
    return a;
}

__global__ void __cluster_dims__(4, 1, 1) __launch_bounds__(512, 1)
rnn_scan_cluster(const float* __restrict__ xz, const float* __restrict__ xh,
                 const float* __restrict__ Uz, const float* __restrict__ Uh,
                 float* __restrict__ hr)
{
    uint32_t crank;
    asm("mov.u32 %0, %%cluster_ctarank;" : "=r"(crank));
    const int b   = blockIdx.x >> 2;
    const int tid = threadIdx.x;
    const int j   = tid & 63;
    const int ig  = tid >> 6;
    const int jg  = (int)crank * 64 + j;
    const int i0  = ig * 32;

    float uz[32], uh[32];
    #pragma unroll
    for (int il = 0; il < 32; il++) {
        uz[il] = Uz[(size_t)(i0 + il)*RR + jg];
        uh[il] = Uh[(size_t)(i0 + il)*RR + jg];
    }

    __shared__ __align__(16) float hbuf[2][RR];
    __shared__ float pz[8][64], ph[8][64];
    if (tid < RR) { hbuf[0][tid] = 0.f; hbuf[1][tid] = 0.f; }
    __syncthreads();
    asm volatile("barrier.cluster.arrive.aligned;" ::: "memory");
    asm volatile("barrier.cluster.wait.aligned;"   ::: "memory");

    const float* xzb = xz + (size_t)b*NSEQ*RR;
    const float* xhb = xh + (size_t)b*NSEQ*RR;
    float*       hrb = hr + (size_t)b*NSEQ*RR;

    for (int t = 0; t < NSEQ; t++) {
        const float* hc = hbuf[t & 1];
        float az = 0.f, ah = 0.f;
        #pragma unroll
        for (int il = 0; il < 32; il += 4) {
            const float4 hv = *(const float4*)&hc[i0 + il];
            az = fmaf(hv.x, uz[il+0], az);  ah = fmaf(hv.x, uh[il+0], ah);
            az = fmaf(hv.y, uz[il+1], az);  ah = fmaf(hv.y, uh[il+1], ah);
            az = fmaf(hv.z, uz[il+2], az);  ah = fmaf(hv.z, uh[il+2], ah);
            az = fmaf(hv.w, uz[il+3], az);  ah = fmaf(hv.w, uh[il+3], ah);
        }
        pz[ig][j] = az;
        ph[ig][j] = ah;
        __syncthreads();
        if (tid < 64) {
            const int jmy = (int)crank * 64 + tid;
            float sz = 0.f, sh = 0.f;
            #pragma unroll
            for (int q = 0; q < 8; q++) { sz += pz[q][tid]; sh += ph[q][tid]; }
            const float hp = hc[jmy];
            const float zp = xzb[(size_t)t*RR + jmy] + sz;
            const float hpre = xhb[(size_t)t*RR + jmy] + sh;
            const float z  = 1.f / (1.f + expf(-zp));
            const float hn = (1.f - z)*hp + z*tanhf(hpre);
            const uint32_t la = smem_u32(&hbuf[(t + 1) & 1][jmy]);
            #pragma unroll
            for (int r = 0; r < 4; r++) {
                uint32_t pa;
                asm volatile("mapa.shared::cluster.u32 %0, %1, %2;" : "=r"(pa) : "r"(la), "r"(r));
                asm volatile("st.shared::cluster.f32 [%0], %1;" :: "r"(pa), "f"(hn));
            }
            hrb[(size_t)t*RR + jmy] = hn;
        }
        asm volatile("barrier.cluster.arrive.aligned;" ::: "memory");
        asm volatile("barrier.cluster.wait.aligned;"   ::: "memory");
    }
}

// ---------------- host-side dispatch ----------------
struct Bo { long s0, s1, s2; };

static void launch_gemm(bool tb, int epi, int M, int N, int K,
                        const float* A, int lda, Bo ba,
                        const float* B, int ldb, Bo bb,
                        float* C, int ldc, Bo bc,
                        int r1, int r2, int nbatch, int causal,
                        const float* E, float scale)
{
    dim3 grid(M/128, N/128, nbatch);   // x = M tiles (activation reuse on head GEMM)
#define GK(TBV, EPV) gemm_k<TBV, EPV><<<grid, 256>>>(A, lda, ba.s0, ba.s1, ba.s2, \
        B, ldb, bb.s0, bb.s1, bb.s2, C, ldc, bc.s0, bc.s1, bc.s2, r1, r2, K, causal, E, scale)
    if (!tb) {
        if      (epi == EPI_STORE) GK(false, EPI_STORE);
        else if (epi == EPI_ACC)   GK(false, EPI_ACC);
        else if (epi == EPI_SCORE) GK(false, EPI_SCORE);
        else                       GK(false, EPI_BVEC);
    } else {
        if      (epi == EPI_STORE) GK(true, EPI_STORE);
        else if (epi == EPI_ACC)   GK(true, EPI_ACC);
        else if (epi == EPI_SCORE) GK(true, EPI_SCORE);
        else                       GK(true, EPI_BVEC);
    }
#undef GK
}

static const Bo B0 = {0, 0, 0};

extern "C" void kernel_launch(void* const* d_in, const int* in_sizes, int n_in,
                              void* d_out, int out_size)
{
    const int*   tokens   = (const int*)  d_in[0];
    const float* embed    = (const float*)d_in[1];
    const float* pb_a     = (const float*)d_in[2];
    const float* pb_w     = (const float*)d_in[3];
    const float* pc_alpha = (const float*)d_in[4];
    const float* W_pc     = (const float*)d_in[5];
    const float* c_pc     = (const float*)d_in[6];
    const float* W_logic  = (const float*)d_in[7];
    const float* ln_g     = (const float*)d_in[8];
    const float* ln_b     = (const float*)d_in[9];
    const float* Wq       = (const float*)d_in[10];
    const float* Wk       = (const float*)d_in[11];
    const float* Wv       = (const float*)d_in[12];
    const float* Wo       = (const float*)d_in[13];
    const float* a_logit  = (const float*)d_in[14];
    const float* Win_ssm  = (const float*)d_in[15];
    const float* Wout_ssm = (const float*)d_in[16];
    const float* Wz       = (const float*)d_in[17];
    const float* Uz       = (const float*)d_in[18];
    const float* Wh       = (const float*)d_in[19];
    const float* Uh       = (const float*)d_in[20];
    const float* Wout_rnn = (const float*)d_in[21];
    const float* res_sc   = (const float*)d_in[22];
    const float* fg       = (const float*)d_in[23];
    const float* fb       = (const float*)d_in[24];
    const float* out_b    = (const float*)d_in[25];
    float* out = (float*)d_out;

    void* pv;
    float *x, *h, *t0, *br, *q, *k, *v, *p, *u, *hs, *xz, *xh, *hr, *bias, *weff;
    cudaGetSymbolAddress(&pv, g_x);    x   = (float*)pv;
    cudaGetSymbolAddress(&pv, g_hb);   h   = (float*)pv;
    cudaGetSymbolAddress(&pv, g_t0);   t0  = (float*)pv;
    cudaGetSymbolAddress(&pv, g_br);   br  = (float*)pv;
    cudaGetSymbolAddress(&pv, g_q);    q   = (float*)pv;
    cudaGetSymbolAddress(&pv, g_k);    k   = (float*)pv;
    cudaGetSymbolAddress(&pv, g_v);    v   = (float*)pv;
    cudaGetSymbolAddress(&pv, g_p);    p   = (float*)pv;
    cudaGetSymbolAddress(&pv, g_u);    u   = (float*)pv;
    cudaGetSymbolAddress(&pv, g_hs);   hs  = (float*)pv;
    cudaGetSymbolAddress(&pv, g_xz);   xz  = (float*)pv;
    cudaGetSymbolAddress(&pv, g_xh);   xh  = (float*)pv;
    cudaGetSymbolAddress(&pv, g_hr);   hr  = (float*)pv;
    cudaGetSymbolAddress(&pv, g_bias); bias= (float*)pv;
    cudaGetSymbolAddress(&pv, g_weff); weff= (float*)pv;

    // ---- precompute positional bias and combined PC projection ----
    bias_kernel<<<4096, 256>>>(pb_a, pb_w, bias);
    weff_kernel<<<4096, 256>>>(pc_alpha, c_pc, W_pc, weff);

    // ---- embed + front projections ----
    embed_kernel<<<BT, 256>>>(tokens, embed, x);
    launch_gemm(false, EPI_STORE, BT, DD, DD, x, DD, B0, weff, DD, B0, t0, DD, B0, 1, 1, 1, 0, nullptr, 0.f);
    vec_add<<<4096, 256>>>(x, t0);
    launch_gemm(false, EPI_STORE, BT, DD, DD, x, DD, B0, W_logic, DD, B0, t0, DD, B0, 1, 1, 1, 0, nullptr, 0.f);
    vec_add_tanh<<<4096, 256>>>(x, t0);

    // ---- layers ----
    for (int l = 0; l < LL; l++) {
        const float* Wq_l = Wq + (size_t)l*DD*512;
        const float* Wk_l = Wk + (size_t)l*DD*256;
        const float* Wv_l = Wv + (size_t)l*DD*512;
        const float* Wo_l = Wo + (size_t)l*DD*DD;
        const float* Wi_l = Win_ssm  + (size_t)l*DD*SS;
        const float* Ws_l = Wout_ssm + (size_t)l*SS*DD;
        const float* Wz_l = Wz + (size_t)l*DD*RR;
        const float* Wh_l = Wh + (size_t)l*DD*RR;
        const float* Uz_l = Uz + (size_t)l*RR*RR;
        const float* Uh_l = Uh + (size_t)l*RR*RR;
        const float* Wr_l = Wout_rnn + (size_t)l*RR*DD;

        ln_kernel<<<BT, 256>>>(x, ln_g + (size_t)l*DD, ln_b + (size_t)l*DD, h);

        launch_gemm(false, EPI_STORE, BT, 512, DD, h, DD, B0, Wq_l, 512, B0, q, 512, B0, 1, 1, 1, 0, nullptr, 0.f);
        launch_gemm(false, EPI_STORE, BT, 256, DD, h, DD, B0, Wk_l, 256, B0, k, 256, B0, 1, 1, 1, 0, nullptr, 0.f);
        launch_gemm(false, EPI_STORE, BT, 512, DD, h, DD, B0, Wv_l, 512, B0, v, 512, B0, 1, 1, 1, 0, nullptr, 0.f);

        // scores: s[b,g,u] = q_slice [N,64] @ k_slice^T, *1/8 + bias, causal mask
        {
            Bo ba = {(long)NSEQ*512, 128, 64};                 // b, g, u strides into q
            Bo bb = {(long)NSEQ*256, 64, 0};                   // b, g strides into k
            Bo bc = {(long)8*NSEQ*NSEQ, (long)2*NSEQ*NSEQ, (long)NSEQ*NSEQ};
            launch_gemm(true, EPI_SCORE, NSEQ, NSEQ, RK, q, 512, ba, k, 256, bb,
                        p, NSEQ, bc, 4, 2, 32, 0, bias, 0.125f);
        }
        softmax_kernel<<<32*NSEQ, 128>>>(p);
        // o = p @ v  -> t0 laid out as [B,N, H*DH]; causal=1 truncates K at diag
        {
            Bo ba = {(long)8*NSEQ*NSEQ, (long)2*NSEQ*NSEQ, (long)NSEQ*NSEQ};
            Bo bb = {(long)NSEQ*512, 128, 0};
            Bo bc = {(long)NSEQ*DD, 256, 128};
            launch_gemm(false, EPI_STORE, NSEQ, DHD, NSEQ, p, NSEQ, ba, v, 512, bb,
                        t0, DD, bc, 4, 2, 32, 1, nullptr, 0.f);
        }
        launch_gemm(false, EPI_STORE, BT, DD, DD, t0, DD, B0, Wo_l, DD, B0, br, DD, B0, 1, 1, 1, 0, nullptr, 0.f);

        // SSM branch (from residual x)
        launch_gemm(false, EPI_STORE, BT, SS, DD, x, DD, B0, Wi_l, SS, B0, u, SS, B0, 1, 1, 1, 0, nullptr, 0.f);
        ssm_scan_kernel<<<BB, SS>>>(u, a_logit + (size_t)l*SS, hs);
        launch_gemm(false, EPI_ACC, BT, DD, SS, hs, SS, B0, Ws_l, DD, B0, br, DD, B0, 1, 1, 1, 0, nullptr, 0.f);

        // gated RNN branch (from residual x)
        launch_gemm(false, EPI_STORE, BT, RR, DD, x, DD, B0, Wz_l, RR, B0, xz, RR, B0, 1, 1, 1, 0, nullptr, 0.f);
        launch_gemm(false, EPI_STORE, BT, RR, DD, x, DD, B0, Wh_l, RR, B0, xh, RR, B0, 1, 1, 1, 0, nullptr, 0.f);
        rnn_scan_cluster<<<BB*4, 512>>>(xz, xh, Uz_l, Uh_l, hr);
        launch_gemm(false, EPI_ACC, BT, DD, RR, hr, RR, B0, Wr_l, DD, B0, br, DD, B0, 1, 1, 1, 0, nullptr, 0.f);

        vec_add_scaled<<<4096, 256>>>(x, br, res_sc, l);
    }

    // ---- final LN + tied head ----
    ln_kernel<<<BT, 256>>>(x, fg, fb, h);
    launch_gemm(true, EPI_BVEC, BT, VV, DD, h, DD, B0, embed, DD, B0, out, VV, B0, 1, 1, 1, 0, out_b, 0.f);
}

// round 12
// speedup vs baseline: 1.1028x; 1.0085x over previous
#include <cuda_runtime.h>
#include <math.h>
#include <stdint.h>

// ---------------- model constants ----------------
#define BB 4
#define NSEQ 1024
#define DD 1024
#define LL 6
#define HH 8
#define GG 4
#define RK 64
#define SS 128
#define RR 256
#define DHD 128
#define VV 32000
#define BT (BB*NSEQ)          // 4096 token rows
#define LOGIC_STRENGTH 0.02f

// ---------------- scratch (static device memory; no allocations) ----------------
__device__ float g_x  [BT*DD];
__device__ float g_hb [BT*DD];
__device__ float g_t0 [BT*DD];
__device__ float g_br [BT*DD];
__device__ float g_qkv[BT*1280];                 // q|k|v interleaved per row
__device__ float g_xzh[BT*640];                  // xz|xh|u  interleaved per row
__device__ float g_p  [(size_t)32*NSEQ*NSEQ];    // [b,g,u,n,m] scores/probs (134 MB)
__device__ float g_hs [BT*SS];
__device__ float g_hr [BT*RR];
__device__ float g_bias[NSEQ*NSEQ];
__device__ float g_weff[DD*DD];
__device__ float g_wqkv[(size_t)LL*DD*1280];     // per-layer Wq|Wk|Wv
__device__ float g_wzhu[(size_t)LL*DD*640];      // per-layer Wz|Wh|Win_ssm

// ---------------- tf32 helpers (3xTF32 error-compensated path) ----------------
__device__ __forceinline__ uint32_t f2tf32(float f) {
    uint32_t r;
    asm("cvt.rna.tf32.f32 %0, %1;" : "=r"(r) : "f"(f));
    return r;
}
__device__ __forceinline__ uint2 split2(float x) {
    uint2 r;
    r.x = f2tf32(x);
    r.y = f2tf32(x - __uint_as_float(r.x));
    return r;
}

// D += A@B via tensor core, m16n8k8 tf32, fp32 accumulate
__device__ __forceinline__ void mma_tf32(float* c, const uint32_t* a, uint32_t b0, uint32_t b1) {
    asm volatile("mma.sync.aligned.m16n8k8.row.col.f32.tf32.tf32.f32 "
        "{%0,%1,%2,%3}, {%4,%5,%6,%7}, {%8,%9}, {%0,%1,%2,%3};"
        : "+f"(c[0]), "+f"(c[1]), "+f"(c[2]), "+f"(c[3])
        : "r"(a[0]), "r"(a[1]), "r"(a[2]), "r"(a[3]), "r"(b0), "r"(b1));
}

// ---------------- generic tiled GEMM via 3xTF32 tensor cores -----------------
// CTA tile 128x128, k-tile 16, 256 thr = 8 warps (4x2), warp tile 32x64.
// hi/lo tf32 split done ONCE on the load->smem path (uint2 {hi,lo} tiles);
// mainloop is pure LDS.64 + MMA. Dynamic smem (67.6 KB), occupancy 2.
#define EPI_STORE 0
#define EPI_ACC   1
#define EPI_SCORE 2
#define EPI_BVEC  3

#define AS_STRIDE 132
#define BS_STRIDE 132
#define SMEM_BYTES (2*16*AS_STRIDE*8 + 2*16*BS_STRIDE*8)   // 67584

template<bool TB, int EPI>
__global__ __launch_bounds__(256, 2)
void gemm_k(const float* __restrict__ A, int lda, long a0, long a1, long a2,
            const float* __restrict__ B, int ldb, long b0s, long b1s, long b2s,
            float* __restrict__ C, int ldc, long c0, long c1, long c2,
            int r1, int r2, int K, int causal,
            const float* __restrict__ E, float scale)
{
    const int bz = blockIdx.z;
    const int z2 = bz % r2;
    const int zt = bz / r2;
    const int z1 = zt % r1;
    const int z0 = zt / r1;
    A += (size_t)z0*a0 + (size_t)z1*a1 + (size_t)z2*a2;
    B += (size_t)z0*b0s + (size_t)z1*b1s + (size_t)z2*b2s;
    C += (size_t)z0*c0 + (size_t)z1*c1 + (size_t)z2*c2;

    const int m0 = blockIdx.x * 128;
    const int n0 = blockIdx.y * 128;
    const int tid = threadIdx.x;

    if (EPI == EPI_SCORE && n0 > m0) {   // tile entirely above diagonal
        for (int idx = tid; idx < 128*128; idx += 256)
            C[(size_t)(m0 + (idx >> 7))*ldc + n0 + (idx & 127)] = -1e9f;
        return;
    }

    const int Keff = causal ? ((m0 + 128 < K) ? (m0 + 128) : K) : K;

    extern __shared__ __align__(16) char dynsmem[];
    uint2 (*As)[16][AS_STRIDE] = (uint2(*)[16][AS_STRIDE])dynsmem;
    uint2 (*Bs)[16][BS_STRIDE] = (uint2(*)[16][BS_STRIDE])(dynsmem + 2*16*AS_STRIDE*8);

    const int lane = tid & 31;
    const int warp = tid >> 5;
    const int gid  = lane >> 2;     // 0..7
    const int tig  = lane & 3;      // 0..3
    const int wm   = (warp >> 1) * 32;   // 0,32,64,96
    const int wn   = (warp & 1) * 64;    // 0,64

    float acc[2][8][4];
    #pragma unroll
    for (int t = 0; t < 2; t++)
        #pragma unroll
        for (int j = 0; j < 8; j++)
            #pragma unroll
            for (int c = 0; c < 4; c++) acc[t][j][c] = 0.f;

    const int arow = tid >> 2;            // 0..63
    const int acol = (tid & 3) << 2;      // 0,4,8,12
    const int brow = tid >> 5;            // 0..7   (non-TB)
    const int bcol = (tid & 31) << 2;     // 0..124 (non-TB)
    const int tbrow = tid >> 1;           // 0..127 (TB)
    const int tbcol = (tid & 1) << 3;     // 0,8    (TB)

    float4 la0, la1, lb0, lb1;

    // ---- prologue: k-tile 0 -> smem[0] (split to tf32 hi/lo at store) ----
    la0 = *(const float4*)(A + (size_t)(m0 + arow     )*lda + acol);
    la1 = *(const float4*)(A + (size_t)(m0 + arow + 64)*lda + acol);
    if (!TB) {
        lb0 = *(const float4*)(B + (size_t)(brow    )*ldb + n0 + bcol);
        lb1 = *(const float4*)(B + (size_t)(brow + 8)*ldb + n0 + bcol);
    } else {
        const float* bp = B + (size_t)(n0 + tbrow)*ldb + tbcol;
        lb0 = *(const float4*)(bp);
        lb1 = *(const float4*)(bp + 4);
    }
    {
        As[0][acol+0][arow] = split2(la0.x); As[0][acol+1][arow] = split2(la0.y);
        As[0][acol+2][arow] = split2(la0.z); As[0][acol+3][arow] = split2(la0.w);
        As[0][acol+0][arow+64] = split2(la1.x); As[0][acol+1][arow+64] = split2(la1.y);
        As[0][acol+2][arow+64] = split2(la1.z); As[0][acol+3][arow+64] = split2(la1.w);
        if (!TB) {
            Bs[0][brow  ][bcol+0] = split2(lb0.x); Bs[0][brow  ][bcol+1] = split2(lb0.y);
            Bs[0][brow  ][bcol+2] = split2(lb0.z); Bs[0][brow  ][bcol+3] = split2(lb0.w);
            Bs[0][brow+8][bcol+0] = split2(lb1.x); Bs[0][brow+8][bcol+1] = split2(lb1.y);
            Bs[0][brow+8][bcol+2] = split2(lb1.z); Bs[0][brow+8][bcol+3] = split2(lb1.w);
        } else {
            Bs[0][tbcol+0][tbrow] = split2(lb0.x); Bs[0][tbcol+1][tbrow] = split2(lb0.y);
            Bs[0][tbcol+2][tbrow] = split2(lb0.z); Bs[0][tbcol+3][tbrow] = split2(lb0.w);
            Bs[0][tbcol+4][tbrow] = split2(lb1.x); Bs[0][tbcol+5][tbrow] = split2(lb1.y);
            Bs[0][tbcol+6][tbrow] = split2(lb1.z); Bs[0][tbcol+7][tbrow] = split2(lb1.w);
        }
    }
    __syncthreads();

    int buf = 0;
    for (int k0 = 0; k0 < Keff; k0 += 16, buf ^= 1) {
        const bool more = (k0 + 16) < Keff;
        if (more) {
            const int kn = k0 + 16;
            la0 = *(const float4*)(A + (size_t)(m0 + arow     )*lda + kn + acol);
            la1 = *(const float4*)(A + (size_t)(m0 + arow + 64)*lda + kn + acol);
            if (!TB) {
                lb0 = *(const float4*)(B + (size_t)(kn + brow    )*ldb + n0 + bcol);
                lb1 = *(const float4*)(B + (size_t)(kn + brow + 8)*ldb + n0 + bcol);
            } else {
                const float* bp = B + (size_t)(n0 + tbrow)*ldb + kn + tbcol;
                lb0 = *(const float4*)(bp);
                lb1 = *(const float4*)(bp + 4);
            }
        }
        // ---- tensor compute on smem[buf]: two k8 chunks, 3xTF32, zero ALU ----
        #pragma unroll
        for (int kc = 0; kc < 16; kc += 8) {
            uint32_t ah[2][4], al[2][4];
            #pragma unroll
            for (int t = 0; t < 2; t++) {
                const int m = wm + t*16 + gid;
                uint2 av0 = As[buf][kc+tig  ][m];
                uint2 av1 = As[buf][kc+tig  ][m+8];
                uint2 av2 = As[buf][kc+tig+4][m];
                uint2 av3 = As[buf][kc+tig+4][m+8];
                ah[t][0]=av0.x; al[t][0]=av0.y;
                ah[t][1]=av1.x; al[t][1]=av1.y;
                ah[t][2]=av2.x; al[t][2]=av2.y;
                ah[t][3]=av3.x; al[t][3]=av3.y;
            }
            #pragma unroll
            for (int j = 0; j < 8; j++) {
                const int n = wn + j*8 + gid;
                const uint2 bv0 = Bs[buf][kc+tig  ][n];
                const uint2 bv1 = Bs[buf][kc+tig+4][n];
                #pragma unroll
                for (int t = 0; t < 2; t++) {
                    mma_tf32(acc[t][j], al[t], bv0.x, bv1.x);   // lo*hi
                    mma_tf32(acc[t][j], ah[t], bv0.y, bv1.y);   // hi*lo
                    mma_tf32(acc[t][j], ah[t], bv0.x, bv1.x);   // hi*hi
                }
            }
        }
        if (!more) break;
        {
            const int nb = buf ^ 1;
            As[nb][acol+0][arow] = split2(la0.x); As[nb][acol+1][arow] = split2(la0.y);
            As[nb][acol+2][arow] = split2(la0.z); As[nb][acol+3][arow] = split2(la0.w);
            As[nb][acol+0][arow+64] = split2(la1.x); As[nb][acol+1][arow+64] = split2(la1.y);
            As[nb][acol+2][arow+64] = split2(la1.z); As[nb][acol+3][arow+64] = split2(la1.w);
            if (!TB) {
                Bs[nb][brow  ][bcol+0] = split2(lb0.x); Bs[nb][brow  ][bcol+1] = split2(lb0.y);
                Bs[nb][brow  ][bcol+2] = split2(lb0.z); Bs[nb][brow  ][bcol+3] = split2(lb0.w);
                Bs[nb][brow+8][bcol+0] = split2(lb1.x); Bs[nb][brow+8][bcol+1] = split2(lb1.y);
                Bs[nb][brow+8][bcol+2] = split2(lb1.z); Bs[nb][brow+8][bcol+3] = split2(lb1.w);
            } else {
                Bs[nb][tbcol+0][tbrow] = split2(lb0.x); Bs[nb][tbcol+1][tbrow] = split2(lb0.y);
                Bs[nb][tbcol+2][tbrow] = split2(lb0.z); Bs[nb][tbcol+3][tbrow] = split2(lb0.w);
                Bs[nb][tbcol+4][tbrow] = split2(lb1.x); Bs[nb][tbcol+5][tbrow] = split2(lb1.y);
                Bs[nb][tbcol+6][tbrow] = split2(lb1.z); Bs[nb][tbcol+7][tbrow] = split2(lb1.w);
            }
        }
        __syncthreads();
    }

    // --- epilogue: (t,j,half) -> row = m0+wm+t*16+gid+half*8, col = n0+wn+j*8+tig*2 ---
    #pragma unroll
    for (int t = 0; t < 2; t++) {
        #pragma unroll
        for (int half = 0; half < 2; half++) {
            const int row = m0 + wm + t*16 + gid + half*8;
            #pragma unroll
            for (int j = 0; j < 8; j++) {
                const int col = n0 + wn + j*8 + tig*2;
                float v0 = acc[t][j][half*2 + 0];
                float v1 = acc[t][j][half*2 + 1];
                float* cp = C + (size_t)row*ldc + col;
                if (EPI == EPI_STORE) {
                    *(float2*)cp = make_float2(v0, v1);
                } else if (EPI == EPI_ACC) {
                    float2 old = *(float2*)cp;
                    *(float2*)cp = make_float2(old.x + v0, old.y + v1);
                } else if (EPI == EPI_SCORE) {
                    float r0 = (col     <= row) ? fmaf(v0, scale, E[(size_t)row*NSEQ + col    ]) : -1e9f;
                    float r1 = (col + 1 <= row) ? fmaf(v1, scale, E[(size_t)row*NSEQ + col + 1]) : -1e9f;
                    *(float2*)cp = make_float2(r0, r1);
                } else { // EPI_BVEC
                    *(float2*)cp = make_float2(v0 + E[col], v1 + E[col + 1]);
                }
            }
        }
    }
}

// ---------------- weight concat kernels ----------------
__global__ void concat_qkv_k(const float* __restrict__ Wq, const float* __restrict__ Wk,
                             const float* __restrict__ Wv, float* __restrict__ out)
{
    const int idx = blockIdx.x * 256 + threadIdx.x;   // LL*DD*1280 total
    const int l = idx / (DD*1280);
    const int rem = idx % (DD*1280);
    const int d = rem / 1280, c = rem % 1280;
    float v;
    if (c < 512)      v = Wq[((size_t)l*DD + d)*512 + c];
    else if (c < 768) v = Wk[((size_t)l*DD + d)*256 + (c - 512)];
    else              v = Wv[((size_t)l*DD + d)*512 + (c - 768)];
    out[idx] = v;
}

__global__ void concat_zhu_k(const float* __restrict__ Wz, const float* __restrict__ Wh,
                             const float* __restrict__ Wi, float* __restrict__ out)
{
    const int idx = blockIdx.x * 256 + threadIdx.x;   // LL*DD*640 total
    const int l = idx / (DD*640);
    const int rem = idx % (DD*640);
    const int d = rem / 640, c = rem % 640;
    float v;
    if (c < 256)      v = Wz[((size_t)l*DD + d)*256 + c];
    else if (c < 512) v = Wh[((size_t)l*DD + d)*256 + (c - 256)];
    else              v = Wi[((size_t)l*DD + d)*128 + (c - 512)];
    out[idx] = v;
}

// ---------------- small kernels ----------------
__global__ void embed_kernel(const int* __restrict__ tok, const float* __restrict__ emb,
                             float* __restrict__ x)
{
    const int row = blockIdx.x;
    const int t = tok[row];
    const float4* src = (const float4*)(emb + (size_t)t*DD);
    float4* dst = (float4*)(x + (size_t)row*DD);
    dst[threadIdx.x] = src[threadIdx.x];
}

__global__ void bias_kernel(const float* __restrict__ pb_a, const float* __restrict__ pb_w,
                            float* __restrict__ bias)
{
    const int idx = blockIdx.x * 256 + threadIdx.x;
    const int n = idx >> 10;
    const int m = idx & 1023;
    const float dn = fabsf((float)(n - m)) * (1.0f / (float)NSEQ);
    const float pi = 3.14159265358979323846f;
    float v = -pb_a[0] * dn * dn;
    v += pb_w[0] * sinf(pi * 1.f * dn);
    v += pb_w[1] * sinf(pi * 2.f * dn);
    v += pb_w[2] * sinf(pi * 3.f * dn);
    bias[idx] = v;
}

__global__ void weff_kernel(const float* __restrict__ alpha, const float* __restrict__ c,
                            const float* __restrict__ Wpc, float* __restrict__ w)
{
    const int idx = blockIdx.x * 256 + threadIdx.x;
    const float s = alpha[0];
    w[idx] = s * (c[0]*Wpc[idx] + c[1]*Wpc[idx + 1048576] + c[2]*Wpc[idx + 2097152]);
}

__global__ void vec_add(float* __restrict__ x, const float* __restrict__ t)
{
    const size_t i = (size_t)(blockIdx.x * 256 + threadIdx.x);
    float4 a = ((const float4*)x)[i];
    float4 b = ((const float4*)t)[i];
    a.x += b.x; a.y += b.y; a.z += b.z; a.w += b.w;
    ((float4*)x)[i] = a;
}

__global__ void vec_add_tanh(float* __restrict__ x, const float* __restrict__ t)
{
    const size_t i = (size_t)(blockIdx.x * 256 + threadIdx.x);
    float4 a = ((const float4*)x)[i];
    float4 b = ((const float4*)t)[i];
    a.x += LOGIC_STRENGTH * tanhf(b.x);
    a.y += LOGIC_STRENGTH * tanhf(b.y);
    a.z += LOGIC_STRENGTH * tanhf(b.z);
    a.w += LOGIC_STRENGTH * tanhf(b.w);
    ((float4*)x)[i] = a;
}

__global__ void vec_add_scaled(float* __restrict__ x, const float* __restrict__ t,
                               const float* __restrict__ scales, int l)
{
    const float s = scales[l];
    const size_t i = (size_t)(blockIdx.x * 256 + threadIdx.x);
    float4 a = ((const float4*)x)[i];
    float4 b = ((const float4*)t)[i];
    a.x += s * b.x; a.y += s * b.y; a.z += s * b.z; a.w += s * b.w;
    ((float4*)x)[i] = a;
}

// LayerNorm over D=1024, one block (256 thr) per row
__global__ __launch_bounds__(256)
void ln_kernel(const float* __restrict__ x, const float* __restrict__ g,
               const float* __restrict__ b, float* __restrict__ y)
{
    const int row = blockIdx.x;
    const float* xr = x + (size_t)row*DD;
    float v[4], s = 0.f, sq = 0.f;
    #pragma unroll
    for (int i = 0; i < 4; i++) {
        v[i] = xr[threadIdx.x + i*256];
        s += v[i]; sq += v[i]*v[i];
    }
    __shared__ float red[16];
    #pragma unroll
    for (int o = 16; o > 0; o >>= 1) {
        s  += __shfl_down_sync(0xffffffffu, s,  o);
        sq += __shfl_down_sync(0xffffffffu, sq, o);
    }
    const int w = threadIdx.x >> 5, lane = threadIdx.x & 31;
    if (lane == 0) { red[w] = s; red[8 + w] = sq; }
    __syncthreads();
    if (threadIdx.x == 0) {
        float ts = 0.f, tq = 0.f;
        #pragma unroll
        for (int k = 0; k < 8; k++) { ts += red[k]; tq += red[8 + k]; }
        red[0] = ts; red[8] = tq;
    }
    __syncthreads();
    const float mean = red[0] * (1.f/1024.f);
    const float var  = red[8] * (1.f/1024.f) - mean*mean;
    const float inv  = rsqrtf(var + 1e-5f);
    float* yr = y + (size_t)row*DD;
    #pragma unroll
    for (int i = 0; i < 4; i++) {
        const int d = threadIdx.x + i*256;
        yr[d] = (v[i] - mean) * inv * g[d] + b[d];
    }
}

// softmax over 1024-wide row, one block (128 thr) per row.
// Causal-aware: row index within the sequence is blockIdx.x & 1023; float4
// groups entirely above the diagonal are NOT loaded (they are -1e9 -> exp 0);
// outputs for those lanes still write 0 through the same path.
__global__ __launch_bounds__(128)
void softmax_kernel(float* __restrict__ p)
{
    float* row = p + (size_t)blockIdx.x * NSEQ;
    const int n = blockIdx.x & (NSEQ - 1);      // sequence row (causal limit)
    float v[8];
    float4 u0, u1;
    const int c0 = threadIdx.x*4;
    const int c1 = 512 + threadIdx.x*4;
    if (c0 <= n) u0 = *(float4*)&row[c0];
    else         u0 = make_float4(-1e9f, -1e9f, -1e9f, -1e9f);
    if (c1 <= n) u1 = *(float4*)&row[c1];
    else         u1 = make_float4(-1e9f, -1e9f, -1e9f, -1e9f);
    v[0]=u0.x; v[1]=u0.y; v[2]=u0.z; v[3]=u0.w;
    v[4]=u1.x; v[5]=u1.y; v[6]=u1.z; v[7]=u1.w;
    float mx = v[0];
    #pragma unroll
    for (int i = 1; i < 8; i++) mx = fmaxf(mx, v[i]);
    __shared__ float red[8];
    #pragma unroll
    for (int o = 16; o > 0; o >>= 1) mx = fmaxf(mx, __shfl_down_sync(0xffffffffu, mx, o));
    const int w = threadIdx.x >> 5, lane = threadIdx.x & 31;
    if (lane == 0) red[w] = mx;
    __syncthreads();
    if (threadIdx.x == 0) red[0] = fmaxf(fmaxf(red[0], red[1]), fmaxf(red[2], red[3]));
    __syncthreads();
    mx = red[0];
    float s = 0.f;
    #pragma unroll
    for (int i = 0; i < 8; i++) { v[i] = expf(v[i] - mx); s += v[i]; }
    #pragma unroll
    for (int o = 16; o > 0; o >>= 1) s += __shfl_down_sync(0xffffffffu, s, o);
    if (lane == 0) red[4 + w] = s;
    __syncthreads();
    if (threadIdx.x == 0) red[4] = red[4] + red[5] + red[6] + red[7];
    __syncthreads();
    const float inv = 1.f / red[4];
    u0.x=v[0]*inv; u0.y=v[1]*inv; u0.z=v[2]*inv; u0.w=v[3]*inv;
    u1.x=v[4]*inv; u1.y=v[5]*inv; u1.z=v[6]*inv; u1.w=v[7]*inv;
    *(float4*)&row[c0] = u0;
    *(float4*)&row[c1] = u1;
}

// diagonal SSM scan: reads u from g_xzh (+512, row stride 640)
__global__ __launch_bounds__(128)
void ssm_scan_kernel(const float* __restrict__ xzh, const float* __restrict__ alog,
                     float* __restrict__ hs)
{
    const int b = blockIdx.x, s = threadIdx.x;
    const float a = 1.f / (1.f + expf(-alog[s]));
    const float* ub = xzh + (size_t)b*NSEQ*640 + 512 + s;
    float*       hb = hs  + (size_t)b*NSEQ*SS + s;
    float h = 0.f;
    #pragma unroll 4
    for (int t = 0; t < NSEQ; t++) {
        h = fmaf(a, h, ub[(size_t)t*640]);
        hb[(size_t)t*SS] = h;
    }
}

// ---------------- gated RNN scan: 4-CTA cluster per batch, U register-resident ----
__device__ __forceinline__ uint32_t smem_u32(const void* p) {
    uint32_t a;
    asm("{ .reg .u64 t; cvta.to.shared.u64 t, %1; cvt.u32.u64 %0, t; }" : "=r"(a) : "l"(p));
    return a;
}

__global__ void __cluster_dims__(4, 1, 1) __launch_bounds__(512, 1)
rnn_scan_cluster(const float* __restrict__ xzh,
                 const float* __restrict__ Uz, const float* __restrict__ Uh,
                 float* __restrict__ hr)
{
    uint32_t crank;
    asm("mov.u32 %0, %%cluster_ctarank;" : "=r"(crank));
    const int b   = blockIdx.x >> 2;
    const int tid = threadIdx.x;
    const int j   = tid & 63;
    const int ig  = tid >> 6;
    const int jg  = (int)crank * 64 + j;
    const int i0  = ig * 32;

    float uz[32], uh[32];
    #pragma unroll
    for (int il = 0; il < 32; il++) {
        uz[il] = Uz[(size_t)(i0 + il)*RR + jg];
        uh[il] = Uh[(size_t)(i0 + il)*RR + jg];
    }

    __shared__ __align__(16) float hbuf[2][RR];
    __shared__ float pz[8][64], ph[8][64];
    if (tid < RR) { hbuf[0][tid] = 0.f; hbuf[1][tid] = 0.f; }
    __syncthreads();
    asm volatile("barrier.cluster.arrive.aligned;" ::: "memory");
    asm volatile("barrier.cluster.wait.aligned;"   ::: "memory");

    const float* xb = xzh + (size_t)b*NSEQ*640;   // xz at +0, xh at +256, stride 640
    float*      hrb = hr  + (size_t)b*NSEQ*RR;

    for (int t = 0; t < NSEQ; t++) {
        const float* hc = hbuf[t & 1];
        float az = 0.f, ah = 0.f;
        #pragma unroll
        for (int il = 0; il < 32; il += 4) {
            const float4 hv = *(const float4*)&hc[i0 + il];
            az = fmaf(hv.x, uz[il+0], az);  ah = fmaf(hv.x, uh[il+0], ah);
            az = fmaf(hv.y, uz[il+1], az);  ah = fmaf(hv.y, uh[il+1], ah);
            az = fmaf(hv.z, uz[il+2], az);  ah = fmaf(hv.z, uh[il+2], ah);
            az = fmaf(hv.w, uz[il+3], az);  ah = fmaf(hv.w, uh[il+3], ah);
        }
        pz[ig][j] = az;
        ph[ig][j] = ah;
        __syncthreads();
        if (tid < 64) {
            const int jmy = (int)crank * 64 + tid;
            float sz = 0.f, sh = 0.f;
            #pragma unroll
            for (int q = 0; q < 8; q++) { sz += pz[q][tid]; sh += ph[q][tid]; }
            const float hp = hc[jmy];
            const float zp   = xb[(size_t)t*640 + jmy]       + sz;
            const float hpre = xb[(size_t)t*640 + 256 + jmy] + sh;
            const float z  = 1.f / (1.f + expf(-zp));
            const float hn = (1.f - z)*hp + z*tanhf(hpre);
            const uint32_t la = smem_u32(&hbuf[(t + 1) & 1][jmy]);
            #pragma unroll
            for (int r = 0; r < 4; r++) {
                uint32_t pa;
                asm volatile("mapa.shared::cluster.u32 %0, %1, %2;" : "=r"(pa) : "r"(la), "r"(r));
                asm volatile("st.shared::cluster.f32 [%0], %1;" :: "r"(pa), "f"(hn));
            }
            hrb[(size_t)t*RR + jmy] = hn;
        }
        asm volatile("barrier.cluster.arrive.aligned;" ::: "memory");
        asm volatile("barrier.cluster.wait.aligned;"   ::: "memory");
    }
}

// ---------------- host-side dispatch ----------------
struct Bo { long s0, s1, s2; };

static void launch_gemm(bool tb, int epi, int M, int N, int K,
                        const float* A, int lda, Bo ba,
                        const float* B, int ldb, Bo bb,
                        float* C, int ldc, Bo bc,
                        int r1, int r2, int nbatch, int causal,
                        const float* E, float scale)
{
    dim3 grid(M/128, N/128, nbatch);
#define GK(TBV, EPV) gemm_k<TBV, EPV><<<grid, 256, SMEM_BYTES>>>(A, lda, ba.s0, ba.s1, ba.s2, \
        B, ldb, bb.s0, bb.s1, bb.s2, C, ldc, bc.s0, bc.s1, bc.s2, r1, r2, K, causal, E, scale)
    if (!tb) {
        if      (epi == EPI_STORE) GK(false, EPI_STORE);
        else if (epi == EPI_ACC)   GK(false, EPI_ACC);
        else if (epi == EPI_SCORE) GK(false, EPI_SCORE);
        else                       GK(false, EPI_BVEC);
    } else {
        if      (epi == EPI_STORE) GK(true, EPI_STORE);
        else if (epi == EPI_ACC)   GK(true, EPI_ACC);
        else if (epi == EPI_SCORE) GK(true, EPI_SCORE);
        else                       GK(true, EPI_BVEC);
    }
#undef GK
}

static void set_gemm_attrs()
{
    cudaFuncSetAttribute(gemm_k<false, EPI_STORE>, cudaFuncAttributeMaxDynamicSharedMemorySize, SMEM_BYTES);
    cudaFuncSetAttribute(gemm_k<false, EPI_ACC  >, cudaFuncAttributeMaxDynamicSharedMemorySize, SMEM_BYTES);
    cudaFuncSetAttribute(gemm_k<false, EPI_SCORE>, cudaFuncAttributeMaxDynamicSharedMemorySize, SMEM_BYTES);
    cudaFuncSetAttribute(gemm_k<false, EPI_BVEC >, cudaFuncAttributeMaxDynamicSharedMemorySize, SMEM_BYTES);
    cudaFuncSetAttribute(gemm_k<true,  EPI_STORE>, cudaFuncAttributeMaxDynamicSharedMemorySize, SMEM_BYTES);
    cudaFuncSetAttribute(gemm_k<true,  EPI_ACC  >, cudaFuncAttributeMaxDynamicSharedMemorySize, SMEM_BYTES);
    cudaFuncSetAttribute(gemm_k<true,  EPI_SCORE>, cudaFuncAttributeMaxDynamicSharedMemorySize, SMEM_BYTES);
    cudaFuncSetAttribute(gemm_k<true,  EPI_BVEC >, cudaFuncAttributeMaxDynamicSharedMemorySize, SMEM_BYTES);
}

static const Bo B0 = {0, 0, 0};

extern "C" void kernel_launch(void* const* d_in, const int* in_sizes, int n_in,
                              void* d_out, int out_size)
{
    const int*   tokens   = (const int*)  d_in[0];
    const float* embed    = (const float*)d_in[1];
    const float* pb_a     = (const float*)d_in[2];
    const float* pb_w     = (const float*)d_in[3];
    const float* pc_alpha = (const float*)d_in[4];
    const float* W_pc     = (const float*)d_in[5];
    const float* c_pc     = (const float*)d_in[6];
    const float* W_logic  = (const float*)d_in[7];
    const float* ln_g     = (const float*)d_in[8];
    const float* ln_b     = (const float*)d_in[9];
    const float* Wq       = (const float*)d_in[10];
    const float* Wk       = (const float*)d_in[11];
    const float* Wv       = (const float*)d_in[12];
    const float* Wo       = (const float*)d_in[13];
    const float* a_logit  = (const float*)d_in[14];
    const float* Win_ssm  = (const float*)d_in[15];
    const float* Wout_ssm = (const float*)d_in[16];
    const float* Wz       = (const float*)d_in[17];
    const float* Uz       = (const float*)d_in[18];
    const float* Wh       = (const float*)d_in[19];
    const float* Uh       = (const float*)d_in[20];
    const float* Wout_rnn = (const float*)d_in[21];
    const float* res_sc   = (const float*)d_in[22];
    const float* fg       = (const float*)d_in[23];
    const float* fb       = (const float*)d_in[24];
    const float* out_b    = (const float*)d_in[25];
    float* out = (float*)d_out;

    set_gemm_attrs();

    void* pv;
    float *x, *h, *t0, *br, *qkv, *xzh, *p, *hs, *hr, *bias, *weff, *wqkv, *wzhu;
    cudaGetSymbolAddress(&pv, g_x);    x    = (float*)pv;
    cudaGetSymbolAddress(&pv, g_hb);   h    = (float*)pv;
    cudaGetSymbolAddress(&pv, g_t0);   t0   = (float*)pv;
    cudaGetSymbolAddress(&pv, g_br);   br   = (float*)pv;
    cudaGetSymbolAddress(&pv, g_qkv);  qkv  = (float*)pv;
    cudaGetSymbolAddress(&pv, g_xzh);  xzh  = (float*)pv;
    cudaGetSymbolAddress(&pv, g_p);    p    = (float*)pv;
    cudaGetSymbolAddress(&pv, g_hs);   hs   = (float*)pv;
    cudaGetSymbolAddress(&pv, g_hr);   hr   = (float*)pv;
    cudaGetSymbolAddress(&pv, g_bias); bias = (float*)pv;
    cudaGetSymbolAddress(&pv, g_weff); weff = (float*)pv;
    cudaGetSymbolAddress(&pv, g_wqkv); wqkv = (float*)pv;
    cudaGetSymbolAddress(&pv, g_wzhu); wzhu = (float*)pv;

    // ---- precompute: bias, combined PC projection, concatenated weights ----
    bias_kernel<<<4096, 256>>>(pb_a, pb_w, bias);
    weff_kernel<<<4096, 256>>>(pc_alpha, c_pc, W_pc, weff);
    concat_qkv_k<<<LL*DD*1280/256, 256>>>(Wq, Wk, Wv, wqkv);
    concat_zhu_k<<<LL*DD*640/256, 256>>>(Wz, Wh, Win_ssm, wzhu);

    // ---- embed + front projections ----
    embed_kernel<<<BT, 256>>>(tokens, embed, x);
    launch_gemm(false, EPI_STORE, BT, DD, DD, x, DD, B0, weff, DD, B0, t0, DD, B0, 1, 1, 1, 0, nullptr, 0.f);
    vec_add<<<4096, 256>>>(x, t0);
    launch_gemm(false, EPI_STORE, BT, DD, DD, x, DD, B0, W_logic, DD, B0, t0, DD, B0, 1, 1, 1, 0, nullptr, 0.f);
    vec_add_tanh<<<4096, 256>>>(x, t0);

    // ---- layers ----
    for (int l = 0; l < LL; l++) {
        const float* Wqkv_l = wqkv + (size_t)l*DD*1280;
        const float* Wzhu_l = wzhu + (size_t)l*DD*640;
        const float* Wo_l = Wo + (size_t)l*DD*DD;
        const float* Ws_l = Wout_ssm + (size_t)l*SS*DD;
        const float* Uz_l = Uz + (size_t)l*RR*RR;
        const float* Uh_l = Uh + (size_t)l*RR*RR;
        const float* Wr_l = Wout_rnn + (size_t)l*RR*DD;

        ln_kernel<<<BT, 256>>>(x, ln_g + (size_t)l*DD, ln_b + (size_t)l*DD, h);

        // fused QKV projection: [BT,1024] @ [1024,1280]
        launch_gemm(false, EPI_STORE, BT, 1280, DD, h, DD, B0, Wqkv_l, 1280, B0, qkv, 1280, B0, 1, 1, 1, 0, nullptr, 0.f);

        // scores: q cols [0,512), k cols [512,768) of qkv rows
        {
            Bo ba = {(long)NSEQ*1280, 128, 64};                // b, g, u strides into q
            Bo bb = {(long)NSEQ*1280, 64, 0};                  // b, g strides into k
            Bo bc = {(long)8*NSEQ*NSEQ, (long)2*NSEQ*NSEQ, (long)NSEQ*NSEQ};
            launch_gemm(true, EPI_SCORE, NSEQ, NSEQ, RK, qkv, 1280, ba, qkv + 512, 1280, bb,
                        p, NSEQ, bc, 4, 2, 32, 0, bias, 0.125f);
        }
        softmax_kernel<<<32*NSEQ, 128>>>(p);
        // o = p @ v (v cols [768,1280)); causal=1 truncates K at diag
        {
            Bo ba = {(long)8*NSEQ*NSEQ, (long)2*NSEQ*NSEQ, (long)NSEQ*NSEQ};
            Bo bb = {(long)NSEQ*1280, 128, 0};
            Bo bc = {(long)NSEQ*DD, 256, 128};
            launch_gemm(false, EPI_STORE, NSEQ, DHD, NSEQ, p, NSEQ, ba, qkv + 768, 1280, bb,
                        t0, DD, bc, 4, 2, 32, 1, nullptr, 0.f);
        }
        launch_gemm(false, EPI_STORE, BT, DD, DD, t0, DD, B0, Wo_l, DD, B0, br, DD, B0, 1, 1, 1, 0, nullptr, 0.f);

        // fused Z|H|U projection from residual x: [BT,1024] @ [1024,640]
        launch_gemm(false, EPI_STORE, BT, 640, DD, x, DD, B0, Wzhu_l, 640, B0, xzh, 640, B0, 1, 1, 1, 0, nullptr, 0.f);

        // SSM branch
        ssm_scan_kernel<<<BB, SS>>>(xzh, a_logit + (size_t)l*SS, hs);
        launch_gemm(false, EPI_ACC, BT, DD, SS, hs, SS, B0, Ws_l, DD, B0, br, DD, B0, 1, 1, 1, 0, nullptr, 0.f);

        // gated RNN branch
        rnn_scan_cluster<<<BB*4, 512>>>(xzh, Uz_l, Uh_l, hr);
        launch_gemm(false, EPI_ACC, BT, DD, RR, hr, RR, B0, Wr_l, DD, B0, br, DD, B0, 1, 1, 1, 0, nullptr, 0.f);

        vec_add_scaled<<<4096, 256>>>(x, br, res_sc, l);
    }

    // ---- final LN + tied head ----
    ln_kernel<<<BT, 256>>>(x, fg, fb, h);
    launch_gemm(true, EPI_BVEC, BT, VV, DD, h, DD, B0, embed, DD, B0, out, VV, B0, 1, 1, 1, 0, out_b, 0.f);
}

// round 14
// speedup vs baseline: 1.2331x; 1.1181x over previous
#include <cuda_runtime.h>
#include <math.h>
#include <stdint.h>

// ---------------- model constants ----------------
#define BB 4
#define NSEQ 1024
#define DD 1024
#define LL 6
#define HH 8
#define GG 4
#define RK 64
#define SS 128
#define RR 256
#define DHD 128
#define VV 32000
#define BT (BB*NSEQ)          // 4096 token rows
#define LOGIC_STRENGTH 0.02f

// ---------------- scratch (static device memory; no allocations) ----------------
__device__ float g_x  [BT*DD];
__device__ float g_hb [BT*DD];
__device__ float g_t0 [BT*DD];
__device__ float g_br [BT*DD];
__device__ float g_qkv[BT*1280];                 // q|k|v interleaved per row
__device__ float g_xzh[BT*640];                  // xz|xh|u  interleaved per row
__device__ float g_p  [(size_t)32*NSEQ*NSEQ];    // [b,g,u,n,m] scores/probs (134 MB)
__device__ float g_hs [BT*SS];
__device__ float g_hr [BT*RR];
__device__ float g_bias[NSEQ*NSEQ];
__device__ float g_weff[DD*DD];
__device__ float g_wqkv[(size_t)LL*DD*1280];     // per-layer Wq|Wk|Wv
__device__ float g_wzhu[(size_t)LL*DD*640];      // per-layer Wz|Wh|Win_ssm

// ---------------- tf32 helpers (3xTF32 error-compensated path) ----------------
__device__ __forceinline__ uint32_t f2tf32(float f) {
    uint32_t r;
    asm("cvt.rna.tf32.f32 %0, %1;" : "=r"(r) : "f"(f));
    return r;
}
__device__ __forceinline__ uint2 split2(float x) {
    uint2 r;
    r.x = f2tf32(x);
    r.y = f2tf32(x - __uint_as_float(r.x));
    return r;
}

// D += A@B via tensor core, m16n8k8 tf32, fp32 accumulate
__device__ __forceinline__ void mma_tf32(float* c, const uint32_t* a, uint32_t b0, uint32_t b1) {
    asm volatile("mma.sync.aligned.m16n8k8.row.col.f32.tf32.tf32.f32 "
        "{%0,%1,%2,%3}, {%4,%5,%6,%7}, {%8,%9}, {%0,%1,%2,%3};"
        : "+f"(c[0]), "+f"(c[1]), "+f"(c[2]), "+f"(c[3])
        : "r"(a[0]), "r"(a[1]), "r"(a[2]), "r"(a[3]), "r"(b0), "r"(b1));
}

// ---------------- generic tiled GEMM via tf32 tensor cores -------------------
// CTA tile 128x128, k-tile 16, 256 thr = 8 warps (4x2), warp tile 32x64.
// hi/lo tf32 split done ONCE on the load->smem path (uint2 {hi,lo} tiles).
// FAST=false: 3xTF32 compensated (fp32-grade). FAST=true: single hi*hi MMA
// (used ONLY for the final head GEMM where no error compounding follows).
#define EPI_STORE 0
#define EPI_ACC   1
#define EPI_SCORE 2
#define EPI_BVEC  3

#define AS_STRIDE 132
#define BS_STRIDE 132
#define SMEM_BYTES (2*16*AS_STRIDE*8 + 2*16*BS_STRIDE*8)   // 67584

template<bool TB, int EPI, bool FAST>
__global__ __launch_bounds__(256, 2)
void gemm_k(const float* __restrict__ A, int lda, long a0, long a1, long a2,
            const float* __restrict__ B, int ldb, long b0s, long b1s, long b2s,
            float* __restrict__ C, int ldc, long c0, long c1, long c2,
            int r1, int r2, int K, int causal,
            const float* __restrict__ E, float scale)
{
    const int bz = blockIdx.z;
    const int z2 = bz % r2;
    const int zt = bz / r2;
    const int z1 = zt % r1;
    const int z0 = zt / r1;
    A += (size_t)z0*a0 + (size_t)z1*a1 + (size_t)z2*a2;
    B += (size_t)z0*b0s + (size_t)z1*b1s + (size_t)z2*b2s;
    C += (size_t)z0*c0 + (size_t)z1*c1 + (size_t)z2*c2;

    const int m0 = blockIdx.x * 128;
    const int n0 = blockIdx.y * 128;
    const int tid = threadIdx.x;

    if (EPI == EPI_SCORE && n0 > m0) {   // tile entirely above diagonal
        for (int idx = tid; idx < 128*128; idx += 256)
            C[(size_t)(m0 + (idx >> 7))*ldc + n0 + (idx & 127)] = -1e9f;
        return;
    }

    const int Keff = causal ? ((m0 + 128 < K) ? (m0 + 128) : K) : K;

    extern __shared__ __align__(16) char dynsmem[];
    uint2 (*As)[16][AS_STRIDE] = (uint2(*)[16][AS_STRIDE])dynsmem;
    uint2 (*Bs)[16][BS_STRIDE] = (uint2(*)[16][BS_STRIDE])(dynsmem + 2*16*AS_STRIDE*8);

    const int lane = tid & 31;
    const int warp = tid >> 5;
    const int gid  = lane >> 2;     // 0..7
    const int tig  = lane & 3;      // 0..3
    const int wm   = (warp >> 1) * 32;   // 0,32,64,96
    const int wn   = (warp & 1) * 64;    // 0,64

    float acc[2][8][4];
    #pragma unroll
    for (int t = 0; t < 2; t++)
        #pragma unroll
        for (int j = 0; j < 8; j++)
            #pragma unroll
            for (int c = 0; c < 4; c++) acc[t][j][c] = 0.f;

    const int arow = tid >> 2;            // 0..63
    const int acol = (tid & 3) << 2;      // 0,4,8,12
    const int brow = tid >> 5;            // 0..7   (non-TB)
    const int bcol = (tid & 31) << 2;     // 0..124 (non-TB)
    const int tbrow = tid >> 1;           // 0..127 (TB)
    const int tbcol = (tid & 1) << 3;     // 0,8    (TB)

    float4 la0, la1, lb0, lb1;

    // ---- prologue: k-tile 0 -> smem[0] (split to tf32 hi/lo at store) ----
    la0 = *(const float4*)(A + (size_t)(m0 + arow     )*lda + acol);
    la1 = *(const float4*)(A + (size_t)(m0 + arow + 64)*lda + acol);
    if (!TB) {
        lb0 = *(const float4*)(B + (size_t)(brow    )*ldb + n0 + bcol);
        lb1 = *(const float4*)(B + (size_t)(brow + 8)*ldb + n0 + bcol);
    } else {
        const float* bp = B + (size_t)(n0 + tbrow)*ldb + tbcol;
        lb0 = *(const float4*)(bp);
        lb1 = *(const float4*)(bp + 4);
    }
    {
        As[0][acol+0][arow] = split2(la0.x); As[0][acol+1][arow] = split2(la0.y);
        As[0][acol+2][arow] = split2(la0.z); As[0][acol+3][arow] = split2(la0.w);
        As[0][acol+0][arow+64] = split2(la1.x); As[0][acol+1][arow+64] = split2(la1.y);
        As[0][acol+2][arow+64] = split2(la1.z); As[0][acol+3][arow+64] = split2(la1.w);
        if (!TB) {
            Bs[0][brow  ][bcol+0] = split2(lb0.x); Bs[0][brow  ][bcol+1] = split2(lb0.y);
            Bs[0][brow  ][bcol+2] = split2(lb0.z); Bs[0][brow  ][bcol+3] = split2(lb0.w);
            Bs[0][brow+8][bcol+0] = split2(lb1.x); Bs[0][brow+8][bcol+1] = split2(lb1.y);
            Bs[0][brow+8][bcol+2] = split2(lb1.z); Bs[0][brow+8][bcol+3] = split2(lb1.w);
        } else {
            Bs[0][tbcol+0][tbrow] = split2(lb0.x); Bs[0][tbcol+1][tbrow] = split2(lb0.y);
            Bs[0][tbcol+2][tbrow] = split2(lb0.z); Bs[0][tbcol+3][tbrow] = split2(lb0.w);
            Bs[0][tbcol+4][tbrow] = split2(lb1.x); Bs[0][tbcol+5][tbrow] = split2(lb1.y);
            Bs[0][tbcol+6][tbrow] = split2(lb1.z); Bs[0][tbcol+7][tbrow] = split2(lb1.w);
        }
    }
    __syncthreads();

    int buf = 0;
    for (int k0 = 0; k0 < Keff; k0 += 16, buf ^= 1) {
        const bool more = (k0 + 16) < Keff;
        if (more) {
            const int kn = k0 + 16;
            la0 = *(const float4*)(A + (size_t)(m0 + arow     )*lda + kn + acol);
            la1 = *(const float4*)(A + (size_t)(m0 + arow + 64)*lda + kn + acol);
            if (!TB) {
                lb0 = *(const float4*)(B + (size_t)(kn + brow    )*ldb + n0 + bcol);
                lb1 = *(const float4*)(B + (size_t)(kn + brow + 8)*ldb + n0 + bcol);
            } else {
                const float* bp = B + (size_t)(n0 + tbrow)*ldb + kn + tbcol;
                lb0 = *(const float4*)(bp);
                lb1 = *(const float4*)(bp + 4);
            }
        }
        // ---- tensor compute on smem[buf]: two k8 chunks ----
        #pragma unroll
        for (int kc = 0; kc < 16; kc += 8) {
            uint32_t ah[2][4], al[2][4];
            #pragma unroll
            for (int t = 0; t < 2; t++) {
                const int m = wm + t*16 + gid;
                uint2 av0 = As[buf][kc+tig  ][m];
                uint2 av1 = As[buf][kc+tig  ][m+8];
                uint2 av2 = As[buf][kc+tig+4][m];
                uint2 av3 = As[buf][kc+tig+4][m+8];
                ah[t][0]=av0.x; al[t][0]=av0.y;
                ah[t][1]=av1.x; al[t][1]=av1.y;
                ah[t][2]=av2.x; al[t][2]=av2.y;
                ah[t][3]=av3.x; al[t][3]=av3.y;
            }
            #pragma unroll
            for (int j = 0; j < 8; j++) {
                const int n = wn + j*8 + gid;
                const uint2 bv0 = Bs[buf][kc+tig  ][n];
                const uint2 bv1 = Bs[buf][kc+tig+4][n];
                #pragma unroll
                for (int t = 0; t < 2; t++) {
                    if (!FAST) {
                        mma_tf32(acc[t][j], al[t], bv0.x, bv1.x);   // lo*hi
                        mma_tf32(acc[t][j], ah[t], bv0.y, bv1.y);   // hi*lo
                    }
                    mma_tf32(acc[t][j], ah[t], bv0.x, bv1.x);       // hi*hi
                }
            }
        }
        if (!more) break;
        {
            const int nb = buf ^ 1;
            As[nb][acol+0][arow] = split2(la0.x); As[nb][acol+1][arow] = split2(la0.y);
            As[nb][acol+2][arow] = split2(la0.z); As[nb][acol+3][arow] = split2(la0.w);
            As[nb][acol+0][arow+64] = split2(la1.x); As[nb][acol+1][arow+64] = split2(la1.y);
            As[nb][acol+2][arow+64] = split2(la1.z); As[nb][acol+3][arow+64] = split2(la1.w);
            if (!TB) {
                Bs[nb][brow  ][bcol+0] = split2(lb0.x); Bs[nb][brow  ][bcol+1] = split2(lb0.y);
                Bs[nb][brow  ][bcol+2] = split2(lb0.z); Bs[nb][brow  ][bcol+3] = split2(lb0.w);
                Bs[nb][brow+8][bcol+0] = split2(lb1.x); Bs[nb][brow+8][bcol+1] = split2(lb1.y);
                Bs[nb][brow+8][bcol+2] = split2(lb1.z); Bs[nb][brow+8][bcol+3] = split2(lb1.w);
            } else {
                Bs[nb][tbcol+0][tbrow] = split2(lb0.x); Bs[nb][tbcol+1][tbrow] = split2(lb0.y);
                Bs[nb][tbcol+2][tbrow] = split2(lb0.z); Bs[nb][tbcol+3][tbrow] = split2(lb0.w);
                Bs[nb][tbcol+4][tbrow] = split2(lb1.x); Bs[nb][tbcol+5][tbrow] = split2(lb1.y);
                Bs[nb][tbcol+6][tbrow] = split2(lb1.z); Bs[nb][tbcol+7][tbrow] = split2(lb1.w);
            }
        }
        __syncthreads();
    }

    // --- epilogue: (t,j,half) -> row = m0+wm+t*16+gid+half*8, col = n0+wn+j*8+tig*2 ---
    #pragma unroll
    for (int t = 0; t < 2; t++) {
        #pragma unroll
        for (int half = 0; half < 2; half++) {
            const int row = m0 + wm + t*16 + gid + half*8;
            #pragma unroll
            for (int j = 0; j < 8; j++) {
                const int col = n0 + wn + j*8 + tig*2;
                float v0 = acc[t][j][half*2 + 0];
                float v1 = acc[t][j][half*2 + 1];
                float* cp = C + (size_t)row*ldc + col;
                if (EPI == EPI_STORE) {
                    *(float2*)cp = make_float2(v0, v1);
                } else if (EPI == EPI_ACC) {
                    float2 old = *(float2*)cp;
                    *(float2*)cp = make_float2(old.x + v0, old.y + v1);
                } else if (EPI == EPI_SCORE) {
                    float r0 = (col     <= row) ? fmaf(v0, scale, E[(size_t)row*NSEQ + col    ]) : -1e9f;
                    float r1 = (col + 1 <= row) ? fmaf(v1, scale, E[(size_t)row*NSEQ + col + 1]) : -1e9f;
                    *(float2*)cp = make_float2(r0, r1);
                } else { // EPI_BVEC
                    *(float2*)cp = make_float2(v0 + E[col], v1 + E[col + 1]);
                }
            }
        }
    }
}

// ---------------- weight concat kernels ----------------
__global__ void concat_qkv_k(const float* __restrict__ Wq, const float* __restrict__ Wk,
                             const float* __restrict__ Wv, float* __restrict__ out)
{
    const int idx = blockIdx.x * 256 + threadIdx.x;   // LL*DD*1280 total
    const int l = idx / (DD*1280);
    const int rem = idx % (DD*1280);
    const int d = rem / 1280, c = rem % 1280;
    float v;
    if (c < 512)      v = Wq[((size_t)l*DD + d)*512 + c];
    else if (c < 768) v = Wk[((size_t)l*DD + d)*256 + (c - 512)];
    else              v = Wv[((size_t)l*DD + d)*512 + (c - 768)];
    out[idx] = v;
}

__global__ void concat_zhu_k(const float* __restrict__ Wz, const float* __restrict__ Wh,
                             const float* __restrict__ Wi, float* __restrict__ out)
{
    const int idx = blockIdx.x * 256 + threadIdx.x;   // LL*DD*640 total
    const int l = idx / (DD*640);
    const int rem = idx % (DD*640);
    const int d = rem / 640, c = rem % 640;
    float v;
    if (c < 256)      v = Wz[((size_t)l*DD + d)*256 + c];
    else if (c < 512) v = Wh[((size_t)l*DD + d)*256 + (c - 256)];
    else              v = Wi[((size_t)l*DD + d)*128 + (c - 512)];
    out[idx] = v;
}

// ---------------- small kernels ----------------
__global__ void embed_kernel(const int* __restrict__ tok, const float* __restrict__ emb,
                             float* __restrict__ x)
{
    const int row = blockIdx.x;
    const int t = tok[row];
    const float4* src = (const float4*)(emb + (size_t)t*DD);
    float4* dst = (float4*)(x + (size_t)row*DD);
    dst[threadIdx.x] = src[threadIdx.x];
}

__global__ void bias_kernel(const float* __restrict__ pb_a, const float* __restrict__ pb_w,
                            float* __restrict__ bias)
{
    const int idx = blockIdx.x * 256 + threadIdx.x;
    const int n = idx >> 10;
    const int m = idx & 1023;
    const float dn = fabsf((float)(n - m)) * (1.0f / (float)NSEQ);
    const float pi = 3.14159265358979323846f;
    float v = -pb_a[0] * dn * dn;
    v += pb_w[0] * sinf(pi * 1.f * dn);
    v += pb_w[1] * sinf(pi * 2.f * dn);
    v += pb_w[2] * sinf(pi * 3.f * dn);
    bias[idx] = v;
}

__global__ void weff_kernel(const float* __restrict__ alpha, const float* __restrict__ c,
                            const float* __restrict__ Wpc, float* __restrict__ w)
{
    const int idx = blockIdx.x * 256 + threadIdx.x;
    const float s = alpha[0];
    w[idx] = s * (c[0]*Wpc[idx] + c[1]*Wpc[idx + 1048576] + c[2]*Wpc[idx + 2097152]);
}

__global__ void vec_add(float* __restrict__ x, const float* __restrict__ t)
{
    const size_t i = (size_t)(blockIdx.x * 256 + threadIdx.x);
    float4 a = ((const float4*)x)[i];
    float4 b = ((const float4*)t)[i];
    a.x += b.x; a.y += b.y; a.z += b.z; a.w += b.w;
    ((float4*)x)[i] = a;
}

__global__ void vec_add_tanh(float* __restrict__ x, const float* __restrict__ t)
{
    const size_t i = (size_t)(blockIdx.x * 256 + threadIdx.x);
    float4 a = ((const float4*)x)[i];
    float4 b = ((const float4*)t)[i];
    a.x += LOGIC_STRENGTH * tanhf(b.x);
    a.y += LOGIC_STRENGTH * tanhf(b.y);
    a.z += LOGIC_STRENGTH * tanhf(b.z);
    a.w += LOGIC_STRENGTH * tanhf(b.w);
    ((float4*)x)[i] = a;
}

__global__ void vec_add_scaled(float* __restrict__ x, const float* __restrict__ t,
                               const float* __restrict__ scales, int l)
{
    const float s = scales[l];
    const size_t i = (size_t)(blockIdx.x * 256 + threadIdx.x);
    float4 a = ((const float4*)x)[i];
    float4 b = ((const float4*)t)[i];
    a.x += s * b.x; a.y += s * b.y; a.z += s * b.z; a.w += s * b.w;
    ((float4*)x)[i] = a;
}

// LayerNorm over D=1024, one block (256 thr) per row
__global__ __launch_bounds__(256)
void ln_kernel(const float* __restrict__ x, const float* __restrict__ g,
               const float* __restrict__ b, float* __restrict__ y)
{
    const int row = blockIdx.x;
    const float* xr = x + (size_t)row*DD;
    float v[4], s = 0.f, sq = 0.f;
    #pragma unroll
    for (int i = 0; i < 4; i++) {
        v[i] = xr[threadIdx.x + i*256];
        s += v[i]; sq += v[i]*v[i];
    }
    __shared__ float red[16];
    #pragma unroll
    for (int o = 16; o > 0; o >>= 1) {
        s  += __shfl_down_sync(0xffffffffu, s,  o);
        sq += __shfl_down_sync(0xffffffffu, sq, o);
    }
    const int w = threadIdx.x >> 5, lane = threadIdx.x & 31;
    if (lane == 0) { red[w] = s; red[8 + w] = sq; }
    __syncthreads();
    if (threadIdx.x == 0) {
        float ts = 0.f, tq = 0.f;
        #pragma unroll
        for (int k = 0; k < 8; k++) { ts += red[k]; tq += red[8 + k]; }
        red[0] = ts; red[8] = tq;
    }
    __syncthreads();
    const float mean = red[0] * (1.f/1024.f);
    const float var  = red[8] * (1.f/1024.f) - mean*mean;
    const float inv  = rsqrtf(var + 1e-5f);
    float* yr = y + (size_t)row*DD;
    #pragma unroll
    for (int i = 0; i < 4; i++) {
        const int d = threadIdx.x + i*256;
        yr[d] = (v[i] - mean) * inv * g[d] + b[d];
    }
}

// softmax over 1024-wide row, one block (128 thr) per row.
// Causal-aware: float4 groups entirely above the diagonal are not loaded.
__global__ __launch_bounds__(128)
void softmax_kernel(float* __restrict__ p)
{
    float* row = p + (size_t)blockIdx.x * NSEQ;
    const int n = blockIdx.x & (NSEQ - 1);      // sequence row (causal limit)
    float v[8];
    float4 u0, u1;
    const int c0 = threadIdx.x*4;
    const int c1 = 512 + threadIdx.x*4;
    if (c0 <= n) u0 = *(float4*)&row[c0];
    else         u0 = make_float4(-1e9f, -1e9f, -1e9f, -1e9f);
    if (c1 <= n) u1 = *(float4*)&row[c1];
    else         u1 = make_float4(-1e9f, -1e9f, -1e9f, -1e9f);
    v[0]=u0.x; v[1]=u0.y; v[2]=u0.z; v[3]=u0.w;
    v[4]=u1.x; v[5]=u1.y; v[6]=u1.z; v[7]=u1.w;
    float mx = v[0];
    #pragma unroll
    for (int i = 1; i < 8; i++) mx = fmaxf(mx, v[i]);
    __shared__ float red[8];
    #pragma unroll
    for (int o = 16; o > 0; o >>= 1) mx = fmaxf(mx, __shfl_down_sync(0xffffffffu, mx, o));
    const int w = threadIdx.x >> 5, lane = threadIdx.x & 31;
    if (lane == 0) red[w] = mx;
    __syncthreads();
    if (threadIdx.x == 0) red[0] = fmaxf(fmaxf(red[0], red[1]), fmaxf(red[2], red[3]));
    __syncthreads();
    mx = red[0];
    float s = 0.f;
    #pragma unroll
    for (int i = 0; i < 8; i++) { v[i] = expf(v[i] - mx); s += v[i]; }
    #pragma unroll
    for (int o = 16; o > 0; o >>= 1) s += __shfl_down_sync(0xffffffffu, s, o);
    if (lane == 0) red[4 + w] = s;
    __syncthreads();
    if (threadIdx.x == 0) red[4] = red[4] + red[5] + red[6] + red[7];
    __syncthreads();
    const float inv = 1.f / red[4];
    u0.x=v[0]*inv; u0.y=v[1]*inv; u0.z=v[2]*inv; u0.w=v[3]*inv;
    u1.x=v[4]*inv; u1.y=v[5]*inv; u1.z=v[6]*inv; u1.w=v[7]*inv;
    *(float4*)&row[c0] = u0;
    *(float4*)&row[c1] = u1;
}

// diagonal SSM scan: reads u from g_xzh (+512, row stride 640)
__global__ __launch_bounds__(128)
void ssm_scan_kernel(const float* __restrict__ xzh, const float* __restrict__ alog,
                     float* __restrict__ hs)
{
    const int b = blockIdx.x, s = threadIdx.x;
    const float a = 1.f / (1.f + expf(-alog[s]));
    const float* ub = xzh + (size_t)b*NSEQ*640 + 512 + s;
    float*       hb = hs  + (size_t)b*NSEQ*SS + s;
    float h = 0.f;
    #pragma unroll 4
    for (int t = 0; t < NSEQ; t++) {
        h = fmaf(a, h, ub[(size_t)t*640]);
        hb[(size_t)t*SS] = h;
    }
}

// ---------------- gated RNN scan: 4-CTA cluster per batch, U register-resident ----
__device__ __forceinline__ uint32_t smem_u32(const void* p) {
    uint32_t a;
    asm("{ .reg .u64 t; cvta.to.shared.u64 t, %1; cvt.u32.u64 %0, t; }" : "=r"(a) : "l"(p));
    return a;
}

__global__ void __cluster_dims__(4, 1, 1) __launch_bounds__(512, 1)
rnn_scan_cluster(const float* __restrict__ xzh,
                 const float* __restrict__ Uz, const float* __restrict__ Uh,
                 float* __restrict__ hr)
{
    uint32_t crank;
    asm("mov.u32 %0, %%cluster_ctarank;" : "=r"(crank));
    const int b   = blockIdx.x >> 2;
    const int tid = threadIdx.x;
    const int j   = tid & 63;
    const int ig  = tid >> 6;
    const int jg  = (int)crank * 64 + j;
    const int i0  = ig * 32;

    float uz[32], uh[32];
    #pragma unroll
    for (int il = 0; il < 32; il++) {
        uz[il] = Uz[(size_t)(i0 + il)*RR + jg];
        uh[il] = Uh[(size_t)(i0 + il)*RR + jg];
    }

    __shared__ __align__(16) float hbuf[2][RR];
    __shared__ float pz[8][64], ph[8][64];
    if (tid < RR) { hbuf[0][tid] = 0.f; hbuf[1][tid] = 0.f; }
    __syncthreads();
    asm volatile("barrier.cluster.arrive.aligned;" ::: "memory");
    asm volatile("barrier.cluster.wait.aligned;"   ::: "memory");

    const float* xb = xzh + (size_t)b*NSEQ*640;   // xz at +0, xh at +256, stride 640
    float*      hrb = hr  + (size_t)b*NSEQ*RR;

    for (int t = 0; t < NSEQ; t++) {
        const float* hc = hbuf[t & 1];
        float az = 0.f, ah = 0.f;
        #pragma unroll
        for (int il = 0; il < 32; il += 4) {
            const float4 hv = *(const float4*)&hc[i0 + il];
            az = fmaf(hv.x, uz[il+0], az);  ah = fmaf(hv.x, uh[il+0], ah);
            az = fmaf(hv.y, uz[il+1], az);  ah = fmaf(hv.y, uh[il+1], ah);
            az = fmaf(hv.z, uz[il+2], az);  ah = fmaf(hv.z, uh[il+2], ah);
            az = fmaf(hv.w, uz[il+3], az);  ah = fmaf(hv.w, uh[il+3], ah);
        }
        pz[ig][j] = az;
        ph[ig][j] = ah;
        __syncthreads();
        if (tid < 64) {
            const int jmy = (int)crank * 64 + tid;
            float sz = 0.f, sh = 0.f;
            #pragma unroll
            for (int q = 0; q < 8; q++) { sz += pz[q][tid]; sh += ph[q][tid]; }
            const float hp = hc[jmy];
            const float zp   = xb[(size_t)t*640 + jmy]       + sz;
            const float hpre = xb[(size_t)t*640 + 256 + jmy] + sh;
            const float z  = 1.f / (1.f + expf(-zp));
            const float hn = (1.f - z)*hp + z*tanhf(hpre);
            const uint32_t la = smem_u32(&hbuf[(t + 1) & 1][jmy]);
            #pragma unroll
            for (int r = 0; r < 4; r++) {
                uint32_t pa;
                asm volatile("mapa.shared::cluster.u32 %0, %1, %2;" : "=r"(pa) : "r"(la), "r"(r));
                asm volatile("st.shared::cluster.f32 [%0], %1;" :: "r"(pa), "f"(hn));
            }
            hrb[(size_t)t*RR + jmy] = hn;
        }
        asm volatile("barrier.cluster.arrive.aligned;" ::: "memory");
        asm volatile("barrier.cluster.wait.aligned;"   ::: "memory");
    }
}

// ---------------- host-side dispatch ----------------
struct Bo { long s0, s1, s2; };

static void launch_gemm(bool tb, int epi, int fast, int M, int N, int K,
                        const float* A, int lda, Bo ba,
                        const float* B, int ldb, Bo bb,
                        float* C, int ldc, Bo bc,
                        int r1, int r2, int nbatch, int causal,
                        const float* E, float scale)
{
    dim3 grid(M/128, N/128, nbatch);
#define GK(TBV, EPV, FV) gemm_k<TBV, EPV, FV><<<grid, 256, SMEM_BYTES>>>(A, lda, ba.s0, ba.s1, ba.s2, \
        B, ldb, bb.s0, bb.s1, bb.s2, C, ldc, bc.s0, bc.s1, bc.s2, r1, r2, K, causal, E, scale)
    if (fast) {
        // fast path only used for the head (TB + BVEC)
        GK(true, EPI_BVEC, true);
    } else if (!tb) {
        if      (epi == EPI_STORE) GK(false, EPI_STORE, false);
        else if (epi == EPI_ACC)   GK(false, EPI_ACC,   false);
        else if (epi == EPI_SCORE) GK(false, EPI_SCORE, false);
        else                       GK(false, EPI_BVEC,  false);
    } else {
        if      (epi == EPI_STORE) GK(true, EPI_STORE, false);
        else if (epi == EPI_ACC)   GK(true, EPI_ACC,   false);
        else if (epi == EPI_SCORE) GK(true, EPI_SCORE, false);
        else                       GK(true, EPI_BVEC,  false);
    }
#undef GK
}

static void set_gemm_attrs()
{
    cudaFuncSetAttribute(gemm_k<false, EPI_STORE, false>, cudaFuncAttributeMaxDynamicSharedMemorySize, SMEM_BYTES);
    cudaFuncSetAttribute(gemm_k<false, EPI_ACC,   false>, cudaFuncAttributeMaxDynamicSharedMemorySize, SMEM_BYTES);
    cudaFuncSetAttribute(gemm_k<false, EPI_SCORE, false>, cudaFuncAttributeMaxDynamicSharedMemorySize, SMEM_BYTES);
    cudaFuncSetAttribute(gemm_k<false, EPI_BVEC,  false>, cudaFuncAttributeMaxDynamicSharedMemorySize, SMEM_BYTES);
    cudaFuncSetAttribute(gemm_k<true,  EPI_STORE, false>, cudaFuncAttributeMaxDynamicSharedMemorySize, SMEM_BYTES);
    cudaFuncSetAttribute(gemm_k<true,  EPI_ACC,   false>, cudaFuncAttributeMaxDynamicSharedMemorySize, SMEM_BYTES);
    cudaFuncSetAttribute(gemm_k<true,  EPI_SCORE, false>, cudaFuncAttributeMaxDynamicSharedMemorySize, SMEM_BYTES);
    cudaFuncSetAttribute(gemm_k<true,  EPI_BVEC,  false>, cudaFuncAttributeMaxDynamicSharedMemorySize, SMEM_BYTES);
    cudaFuncSetAttribute(gemm_k<true,  EPI_BVEC,  true >, cudaFuncAttributeMaxDynamicSharedMemorySize, SMEM_BYTES);
}

static const Bo B0 = {0, 0, 0};

extern "C" void kernel_launch(void* const* d_in, const int* in_sizes, int n_in,
                              void* d_out, int out_size)
{
    const int*   tokens   = (const int*)  d_in[0];
    const float* embed    = (const float*)d_in[1];
    const float* pb_a     = (const float*)d_in[2];
    const float* pb_w     = (const float*)d_in[3];
    const float* pc_alpha = (const float*)d_in[4];
    const float* W_pc     = (const float*)d_in[5];
    const float* c_pc     = (const float*)d_in[6];
    const float* W_logic  = (const float*)d_in[7];
    const float* ln_g     = (const float*)d_in[8];
    const float* ln_b     = (const float*)d_in[9];
    const float* Wq       = (const float*)d_in[10];
    const float* Wk       = (const float*)d_in[11];
    const float* Wv       = (const float*)d_in[12];
    const float* Wo       = (const float*)d_in[13];
    const float* a_logit  = (const float*)d_in[14];
    const float* Win_ssm  = (const float*)d_in[15];
    const float* Wout_ssm = (const float*)d_in[16];
    const float* Wz       = (const float*)d_in[17];
    const float* Uz       = (const float*)d_in[18];
    const float* Wh       = (const float*)d_in[19];
    const float* Uh       = (const float*)d_in[20];
    const float* Wout_rnn = (const float*)d_in[21];
    const float* res_sc   = (const float*)d_in[22];
    const float* fg       = (const float*)d_in[23];
    const float* fb       = (const float*)d_in[24];
    const float* out_b    = (const float*)d_in[25];
    float* out = (float*)d_out;

    set_gemm_attrs();

    void* pv;
    float *x, *h, *t0, *br, *qkv, *xzh, *p, *hs, *hr, *bias, *weff, *wqkv, *wzhu;
    cudaGetSymbolAddress(&pv, g_x);    x    = (float*)pv;
    cudaGetSymbolAddress(&pv, g_hb);   h    = (float*)pv;
    cudaGetSymbolAddress(&pv, g_t0);   t0   = (float*)pv;
    cudaGetSymbolAddress(&pv, g_br);   br   = (float*)pv;
    cudaGetSymbolAddress(&pv, g_qkv);  qkv  = (float*)pv;
    cudaGetSymbolAddress(&pv, g_xzh);  xzh  = (float*)pv;
    cudaGetSymbolAddress(&pv, g_p);    p    = (float*)pv;
    cudaGetSymbolAddress(&pv, g_hs);   hs   = (float*)pv;
    cudaGetSymbolAddress(&pv, g_hr);   hr   = (float*)pv;
    cudaGetSymbolAddress(&pv, g_bias); bias = (float*)pv;
    cudaGetSymbolAddress(&pv, g_weff); weff = (float*)pv;
    cudaGetSymbolAddress(&pv, g_wqkv); wqkv = (float*)pv;
    cudaGetSymbolAddress(&pv, g_wzhu); wzhu = (float*)pv;

    // ---- precompute: bias, combined PC projection, concatenated weights ----
    bias_kernel<<<4096, 256>>>(pb_a, pb_w, bias);
    weff_kernel<<<4096, 256>>>(pc_alpha, c_pc, W_pc, weff);
    concat_qkv_k<<<LL*DD*1280/256, 256>>>(Wq, Wk, Wv, wqkv);
    concat_zhu_k<<<LL*DD*640/256, 256>>>(Wz, Wh, Win_ssm, wzhu);

    // ---- embed + front projections ----
    embed_kernel<<<BT, 256>>>(tokens, embed, x);
    launch_gemm(false, EPI_STORE, 0, BT, DD, DD, x, DD, B0, weff, DD, B0, t0, DD, B0, 1, 1, 1, 0, nullptr, 0.f);
    vec_add<<<4096, 256>>>(x, t0);
    launch_gemm(false, EPI_STORE, 0, BT, DD, DD, x, DD, B0, W_logic, DD, B0, t0, DD, B0, 1, 1, 1, 0, nullptr, 0.f);
    vec_add_tanh<<<4096, 256>>>(x, t0);

    // ---- layers ----
    for (int l = 0; l < LL; l++) {
        const float* Wqkv_l = wqkv + (size_t)l*DD*1280;
        const float* Wzhu_l = wzhu + (size_t)l*DD*640;
        const float* Wo_l = Wo + (size_t)l*DD*DD;
        const float* Ws_l = Wout_ssm + (size_t)l*SS*DD;
        const float* Uz_l = Uz + (size_t)l*RR*RR;
        const float* Uh_l = Uh + (size_t)l*RR*RR;
        const float* Wr_l = Wout_rnn + (size_t)l*RR*DD;

        ln_kernel<<<BT, 256>>>(x, ln_g + (size_t)l*DD, ln_b + (size_t)l*DD, h);

        // fused QKV projection: [BT,1024] @ [1024,1280]
        launch_gemm(false, EPI_STORE, 0, BT, 1280, DD, h, DD, B0, Wqkv_l, 1280, B0, qkv, 1280, B0, 1, 1, 1, 0, nullptr, 0.f);

        // scores: q cols [0,512), k cols [512,768) of qkv rows
        {
            Bo ba = {(long)NSEQ*1280, 128, 64};                // b, g, u strides into q
            Bo bb = {(long)NSEQ*1280, 64, 0};                  // b, g strides into k
            Bo bc = {(long)8*NSEQ*NSEQ, (long)2*NSEQ*NSEQ, (long)NSEQ*NSEQ};
            launch_gemm(true, EPI_SCORE, 0, NSEQ, NSEQ, RK, qkv, 1280, ba, qkv + 512, 1280, bb,
                        p, NSEQ, bc, 4, 2, 32, 0, bias, 0.125f);
        }
        softmax_kernel<<<32*NSEQ, 128>>>(p);
        // o = p @ v (v cols [768,1280)); causal=1 truncates K at diag
        {
            Bo ba = {(long)8*NSEQ*NSEQ, (long)2*NSEQ*NSEQ, (long)NSEQ*NSEQ};
            Bo bb = {(long)NSEQ*1280, 128, 0};
            Bo bc = {(long)NSEQ*DD, 256, 128};
            launch_gemm(false, EPI_STORE, 0, NSEQ, DHD, NSEQ, p, NSEQ, ba, qkv + 768, 1280, bb,
                        t0, DD, bc, 4, 2, 32, 1, nullptr, 0.f);
        }
        launch_gemm(false, EPI_STORE, 0, BT, DD, DD, t0, DD, B0, Wo_l, DD, B0, br, DD, B0, 1, 1, 1, 0, nullptr, 0.f);

        // fused Z|H|U projection from residual x: [BT,1024] @ [1024,640]
        launch_gemm(false, EPI_STORE, 0, BT, 640, DD, x, DD, B0, Wzhu_l, 640, B0, xzh, 640, B0, 1, 1, 1, 0, nullptr, 0.f);

        // SSM branch
        ssm_scan_kernel<<<BB, SS>>>(xzh, a_logit + (size_t)l*SS, hs);
        launch_gemm(false, EPI_ACC, 0, BT, DD, SS, hs, SS, B0, Ws_l, DD, B0, br, DD, B0, 1, 1, 1, 0, nullptr, 0.f);

        // gated RNN branch
        rnn_scan_cluster<<<BB*4, 512>>>(xzh, Uz_l, Uh_l, hr);
        launch_gemm(false, EPI_ACC, 0, BT, DD, RR, hr, RR, B0, Wr_l, DD, B0, br, DD, B0, 1, 1, 1, 0, nullptr, 0.f);

        vec_add_scaled<<<4096, 256>>>(x, br, res_sc, l);
    }

    // ---- final LN + tied head (1xTF32 fast path: last op, no compounding) ----
    ln_kernel<<<BT, 256>>>(x, fg, fb, h);
    launch_gemm(true, EPI_BVEC, 1, BT, VV, DD, h, DD, B0, embed, DD, B0, out, VV, B0, 1, 1, 1, 0, out_b, 0.f);
}